// round 1
// baseline (speedup 1.0000x reference)
#include <cuda_runtime.h>
#include <math.h>

#define N_NODES 100000
#define N_EDGES 1600000
#define HID 32

// ---------------- device scratch (no allocs allowed) ----------------
__device__ int    g_i64;                    // 1 if edge_index is int64, 0 if int32
__device__ float4 g_x  [N_NODES * 8];       // node embedding x   [N,32]
__device__ float4 g_A  [N_NODES * 8];       // x @ msg_w1[0:32]   [N,32]
__device__ float4 g_B  [N_NODES * 8];       // x @ msg_w1[32:64]  [N,32]
__device__ float4 g_agg[N_NODES * 8];       // sum of relu(h) per dst [N,32]
__device__ float  g_dist[N_EDGES];
__device__ float  g_deg [N_NODES];

// ---------------- small helpers ----------------
__device__ __forceinline__ float4 fma4(float f, float4 w, float4 a) {
    a.x = fmaf(f, w.x, a.x); a.y = fmaf(f, w.y, a.y);
    a.z = fmaf(f, w.z, a.z); a.w = fmaf(f, w.w, a.w);
    return a;
}
__device__ __forceinline__ float4 add4(float4 a, float4 b) {
    a.x += b.x; a.y += b.y; a.z += b.z; a.w += b.w; return a;
}
__device__ __forceinline__ float4 relu4(float4 v) {
    v.x = fmaxf(v.x, 0.f); v.y = fmaxf(v.y, 0.f);
    v.z = fmaxf(v.z, 0.f); v.w = fmaxf(v.w, 0.f); return v;
}
// compile-time component select (loops using this must be fully unrolled)
#define COMP(v, c) ((c) == 0 ? (v).x : (c) == 1 ? (v).y : (c) == 2 ? (v).z : (v).w)

// ---------------- edge-index dtype detection ----------------
// int64 layout: words are [lo, hi, lo, hi, ...] with hi == 0 (values < 100000).
// int32 layout: odd words are src[1], src[3], ... (random in [0,1e5), ~surely nonzero).
__global__ void detect_kernel(const int* ei32) {
    if (blockIdx.x == 0 && threadIdx.x == 0) {
        int any = 0;
        for (int i = 1; i < 512; i += 2) any |= ei32[i];
        g_i64 = (any == 0) ? 1 : 0;
    }
}

__global__ void zero_deg_kernel() {
    int n = blockIdx.x * blockDim.x + threadIdx.x;
    if (n < N_NODES) g_deg[n] = 0.f;
}

// dist per edge (constant across layers) + degree per dst node
__global__ void prep_kernel(const void* ei, const float* __restrict__ pos) {
    int e = blockIdx.x * blockDim.x + threadIdx.x;
    if (e >= N_EDGES) return;
    int src, dst;
    if (g_i64) {
        const long long* p = (const long long*)ei;
        src = (int)p[e]; dst = (int)p[N_EDGES + e];
    } else {
        const int* p = (const int*)ei;
        src = p[e]; dst = p[N_EDGES + e];
    }
    float dx = pos[dst * 3 + 0] - pos[src * 3 + 0];
    float dy = pos[dst * 3 + 1] - pos[src * 3 + 1];
    float dz = pos[dst * 3 + 2] - pos[src * 3 + 2];
    g_dist[e] = sqrtf(dx * dx + dy * dy + dz * dz);
    atomicAdd(&g_deg[dst], 1.0f);
}

// ---------------- encoder: x = relu(feat@w1+b1)@w2+b2 ----------------
__global__ void __launch_bounds__(128) encoder_kernel(
    const float* __restrict__ feat,
    const float* __restrict__ w1, const float* __restrict__ b1,
    const float* __restrict__ w2, const float* __restrict__ b2) {
    __shared__ float4 s_w1[64 * 8];
    __shared__ float4 s_w2[32 * 8];
    __shared__ float4 s_b1[8], s_b2[8];
    for (int i = threadIdx.x; i < 512; i += 128) s_w1[i] = ((const float4*)w1)[i];
    for (int i = threadIdx.x; i < 256; i += 128) s_w2[i] = ((const float4*)w2)[i];
    if (threadIdx.x < 8) {
        s_b1[threadIdx.x] = ((const float4*)b1)[threadIdx.x];
        s_b2[threadIdx.x] = ((const float4*)b2)[threadIdx.x];
    }
    __syncthreads();
    int n = blockIdx.x * blockDim.x + threadIdx.x;
    if (n >= N_NODES) return;

    const float* frow = feat + (size_t)n * 64;
    float4 h[8];
#pragma unroll
    for (int i = 0; i < 8; i++) h[i] = s_b1[i];
    for (int k = 0; k < 64; k++) {
        float f = frow[k];
#pragma unroll
        for (int i = 0; i < 8; i++) h[i] = fma4(f, s_w1[k * 8 + i], h[i]);
    }
#pragma unroll
    for (int i = 0; i < 8; i++) h[i] = relu4(h[i]);

    float4 y[8];
#pragma unroll
    for (int i = 0; i < 8; i++) y[i] = s_b2[i];
#pragma unroll
    for (int k = 0; k < 32; k++) {
        float f = COMP(h[k >> 2], k & 3);
#pragma unroll
        for (int i = 0; i < 8; i++) y[i] = fma4(f, s_w2[k * 8 + i], y[i]);
    }
#pragma unroll
    for (int i = 0; i < 8; i++) g_x[(size_t)n * 8 + i] = y[i];
}

// ---------------- per layer: A = x@w1a, B = x@w1b, zero agg ----------------
__global__ void __launch_bounds__(128) ab_kernel(const float* __restrict__ w1) {
    __shared__ float4 s_wa[32 * 8];
    __shared__ float4 s_wb[32 * 8];
    for (int i = threadIdx.x; i < 256; i += 128) {
        s_wa[i] = ((const float4*)w1)[i];
        s_wb[i] = ((const float4*)(w1 + 1024))[i];
    }
    __syncthreads();
    int n = blockIdx.x * blockDim.x + threadIdx.x;
    if (n >= N_NODES) return;

    float4 xr[8];
#pragma unroll
    for (int i = 0; i < 8; i++) xr[i] = g_x[(size_t)n * 8 + i];

    float4 a[8];
#pragma unroll
    for (int i = 0; i < 8; i++) a[i] = make_float4(0.f, 0.f, 0.f, 0.f);
#pragma unroll
    for (int k = 0; k < 32; k++) {
        float f = COMP(xr[k >> 2], k & 3);
#pragma unroll
        for (int i = 0; i < 8; i++) a[i] = fma4(f, s_wa[k * 8 + i], a[i]);
    }
#pragma unroll
    for (int i = 0; i < 8; i++) g_A[(size_t)n * 8 + i] = a[i];

    float4 b[8];
#pragma unroll
    for (int i = 0; i < 8; i++) b[i] = make_float4(0.f, 0.f, 0.f, 0.f);
#pragma unroll
    for (int k = 0; k < 32; k++) {
        float f = COMP(xr[k >> 2], k & 3);
#pragma unroll
        for (int i = 0; i < 8; i++) b[i] = fma4(f, s_wb[k * 8 + i], b[i]);
    }
    float4 z = make_float4(0.f, 0.f, 0.f, 0.f);
#pragma unroll
    for (int i = 0; i < 8; i++) {
        g_B[(size_t)n * 8 + i] = b[i];
        g_agg[(size_t)n * 8 + i] = z;
    }
}

// ---------------- per layer, per edge: agg[dst] += relu(A[dst]+B[src]+d*c+b1) ----------------
__global__ void __launch_bounds__(256) edge_kernel(
    const void* ei, const float* __restrict__ w1c, const float* __restrict__ b1) {
    __shared__ float4 s_c[8], s_b[8];
    if (threadIdx.x < 8) {
        s_c[threadIdx.x] = ((const float4*)w1c)[threadIdx.x];
        s_b[threadIdx.x] = ((const float4*)b1)[threadIdx.x];
    }
    __syncthreads();
    int e = blockIdx.x * blockDim.x + threadIdx.x;
    if (e >= N_EDGES) return;

    int src, dst;
    if (g_i64) {
        const long long* p = (const long long*)ei;
        src = (int)p[e]; dst = (int)p[N_EDGES + e];
    } else {
        const int* p = (const int*)ei;
        src = p[e]; dst = p[N_EDGES + e];
    }
    float d = g_dist[e];
    const float4* Ad = &g_A[(size_t)dst * 8];
    const float4* Bs = &g_B[(size_t)src * 8];
    float* outp = (float*)&g_agg[(size_t)dst * 8];
#pragma unroll
    for (int i = 0; i < 8; i++) {
        float4 a = Ad[i];
        float4 b = Bs[i];
        float4 h = relu4(fma4(d, s_c[i], add4(add4(a, b), s_b[i])));
        asm volatile("red.global.add.v4.f32 [%0], {%1, %2, %3, %4};"
                     :: "l"(outp + i * 4), "f"(h.x), "f"(h.y), "f"(h.z), "f"(h.w)
                     : "memory");
    }
}

// ---------------- per layer, per node: agg=aggH@mw2+deg*mb2; x=relu([x|agg]@uw1+ub1)@uw2+ub2 ----------------
__global__ void __launch_bounds__(128) update_kernel(
    const float* __restrict__ mw2, const float* __restrict__ mb2,
    const float* __restrict__ uw1, const float* __restrict__ ub1,
    const float* __restrict__ uw2, const float* __restrict__ ub2) {
    __shared__ float4 s_mw2[256];
    __shared__ float4 s_u1a[256];
    __shared__ float4 s_u1b[256];
    __shared__ float4 s_uw2[256];
    __shared__ float4 s_mb2[8], s_ub1[8], s_ub2[8];
    for (int i = threadIdx.x; i < 256; i += 128) {
        s_mw2[i] = ((const float4*)mw2)[i];
        s_u1a[i] = ((const float4*)uw1)[i];
        s_u1b[i] = ((const float4*)(uw1 + 1024))[i];
        s_uw2[i] = ((const float4*)uw2)[i];
    }
    if (threadIdx.x < 8) {
        s_mb2[threadIdx.x] = ((const float4*)mb2)[threadIdx.x];
        s_ub1[threadIdx.x] = ((const float4*)ub1)[threadIdx.x];
        s_ub2[threadIdx.x] = ((const float4*)ub2)[threadIdx.x];
    }
    __syncthreads();
    int n = blockIdx.x * blockDim.x + threadIdx.x;
    if (n >= N_NODES) return;

    float deg = g_deg[n];
    float4 ar[8];
#pragma unroll
    for (int i = 0; i < 8; i++) ar[i] = g_agg[(size_t)n * 8 + i];

    // agg = aggH @ mw2 + deg * mb2   (segment_sum of second msg-MLP layer)
    float4 agg[8];
#pragma unroll
    for (int i = 0; i < 8; i++) {
        float4 bb = s_mb2[i];
        agg[i] = make_float4(deg * bb.x, deg * bb.y, deg * bb.z, deg * bb.w);
    }
#pragma unroll
    for (int k = 0; k < 32; k++) {
        float f = COMP(ar[k >> 2], k & 3);
#pragma unroll
        for (int i = 0; i < 8; i++) agg[i] = fma4(f, s_mw2[k * 8 + i], agg[i]);
    }

    float4 xr[8];
#pragma unroll
    for (int i = 0; i < 8; i++) xr[i] = g_x[(size_t)n * 8 + i];

    // u = relu(x @ u1a + agg @ u1b + ub1)
    float4 u[8];
#pragma unroll
    for (int i = 0; i < 8; i++) u[i] = s_ub1[i];
#pragma unroll
    for (int k = 0; k < 32; k++) {
        float f = COMP(xr[k >> 2], k & 3);
#pragma unroll
        for (int i = 0; i < 8; i++) u[i] = fma4(f, s_u1a[k * 8 + i], u[i]);
    }
#pragma unroll
    for (int k = 0; k < 32; k++) {
        float f = COMP(agg[k >> 2], k & 3);
#pragma unroll
        for (int i = 0; i < 8; i++) u[i] = fma4(f, s_u1b[k * 8 + i], u[i]);
    }
#pragma unroll
    for (int i = 0; i < 8; i++) u[i] = relu4(u[i]);

    // x = u @ uw2 + ub2
    float4 y[8];
#pragma unroll
    for (int i = 0; i < 8; i++) y[i] = s_ub2[i];
#pragma unroll
    for (int k = 0; k < 32; k++) {
        float f = COMP(u[k >> 2], k & 3);
#pragma unroll
        for (int i = 0; i < 8; i++) y[i] = fma4(f, s_uw2[k * 8 + i], y[i]);
    }
#pragma unroll
    for (int i = 0; i < 8; i++) g_x[(size_t)n * 8 + i] = y[i];
}

// ---------------- output: out = x @ out_w + out_b ----------------
__global__ void __launch_bounds__(128) out_kernel(
    const float* __restrict__ ow, const float* __restrict__ ob, float* __restrict__ out) {
    __shared__ float4 s_w[256];
    __shared__ float4 s_b[8];
    for (int i = threadIdx.x; i < 256; i += 128) s_w[i] = ((const float4*)ow)[i];
    if (threadIdx.x < 8) s_b[threadIdx.x] = ((const float4*)ob)[threadIdx.x];
    __syncthreads();
    int n = blockIdx.x * blockDim.x + threadIdx.x;
    if (n >= N_NODES) return;

    float4 xr[8];
#pragma unroll
    for (int i = 0; i < 8; i++) xr[i] = g_x[(size_t)n * 8 + i];
    float4 y[8];
#pragma unroll
    for (int i = 0; i < 8; i++) y[i] = s_b[i];
#pragma unroll
    for (int k = 0; k < 32; k++) {
        float f = COMP(xr[k >> 2], k & 3);
#pragma unroll
        for (int i = 0; i < 8; i++) y[i] = fma4(f, s_w[k * 8 + i], y[i]);
    }
    float4* orow = (float4*)(out + (size_t)n * 32);
#pragma unroll
    for (int i = 0; i < 8; i++) orow[i] = y[i];
}

// ---------------- launch ----------------
extern "C" void kernel_launch(void* const* d_in, const int* in_sizes, int n_in,
                              void* d_out, int out_size) {
    const float* node_feat = (const float*)d_in[0];
    const float* pos       = (const float*)d_in[1];
    const void*  ei        = d_in[2];
    const float* enc_w1    = (const float*)d_in[3];
    const float* enc_b1    = (const float*)d_in[4];
    const float* enc_w2    = (const float*)d_in[5];
    const float* enc_b2    = (const float*)d_in[6];
    const float* msg_w1    = (const float*)d_in[7];   // [3, 65, 32]
    const float* msg_b1    = (const float*)d_in[8];   // [3, 32]
    const float* msg_w2    = (const float*)d_in[9];   // [3, 32, 32]
    const float* msg_b2    = (const float*)d_in[10];  // [3, 32]
    const float* upd_w1    = (const float*)d_in[11];  // [3, 64, 32]
    const float* upd_b1    = (const float*)d_in[12];
    const float* upd_w2    = (const float*)d_in[13];
    const float* upd_b2    = (const float*)d_in[14];
    const float* out_w     = (const float*)d_in[15];
    const float* out_b     = (const float*)d_in[16];
    float* out = (float*)d_out;

    const int NODE_BLOCKS = (N_NODES + 127) / 128;
    const int EDGE_BLOCKS = (N_EDGES + 255) / 256;

    detect_kernel<<<1, 32>>>((const int*)ei);
    zero_deg_kernel<<<(N_NODES + 255) / 256, 256>>>();
    prep_kernel<<<EDGE_BLOCKS, 256>>>(ei, pos);
    encoder_kernel<<<NODE_BLOCKS, 128>>>(node_feat, enc_w1, enc_b1, enc_w2, enc_b2);

    for (int l = 0; l < 3; l++) {
        const float* w1  = msg_w1 + (size_t)l * 65 * 32;
        ab_kernel<<<NODE_BLOCKS, 128>>>(w1);
        edge_kernel<<<EDGE_BLOCKS, 256>>>(ei, w1 + 64 * 32, msg_b1 + (size_t)l * 32);
        update_kernel<<<NODE_BLOCKS, 128>>>(
            msg_w2 + (size_t)l * 32 * 32, msg_b2 + (size_t)l * 32,
            upd_w1 + (size_t)l * 64 * 32, upd_b1 + (size_t)l * 32,
            upd_w2 + (size_t)l * 32 * 32, upd_b2 + (size_t)l * 32);
    }
    out_kernel<<<NODE_BLOCKS, 128>>>(out_w, out_b, out);
}

// round 2
// speedup vs baseline: 1.6911x; 1.6911x over previous
#include <cuda_runtime.h>
#include <math.h>

#define N_NODES 100000
#define N_EDGES 1600000
#define HID 32

// ---------------- device scratch (no allocs allowed) ----------------
__device__ int    g_i64;                    // 1 if edge_index is int64, 0 if int32
__device__ float4 g_x  [N_NODES * 8];       // node embedding x   [N,32]
__device__ float4 g_A  [N_NODES * 8];       // x @ msg_w1[0:32]   [N,32]
__device__ float4 g_B  [N_NODES * 8];       // x @ msg_w1[32:64]  [N,32]
__device__ float4 g_agg[N_NODES * 8];       // sum of relu(h) per dst [N,32]
__device__ float  g_dist[N_EDGES];
__device__ float  g_deg [N_NODES];
__device__ int    g_src [N_EDGES];          // decoded int32 edge index
__device__ int    g_dst [N_EDGES];

// ---------------- small helpers ----------------
__device__ __forceinline__ float4 fma4(float f, float4 w, float4 a) {
    a.x = fmaf(f, w.x, a.x); a.y = fmaf(f, w.y, a.y);
    a.z = fmaf(f, w.z, a.z); a.w = fmaf(f, w.w, a.w);
    return a;
}
__device__ __forceinline__ float4 add4(float4 a, float4 b) {
    a.x += b.x; a.y += b.y; a.z += b.z; a.w += b.w; return a;
}
__device__ __forceinline__ float4 relu4(float4 v) {
    v.x = fmaxf(v.x, 0.f); v.y = fmaxf(v.y, 0.f);
    v.z = fmaxf(v.z, 0.f); v.w = fmaxf(v.w, 0.f); return v;
}
// compile-time component select (loops using this must be fully unrolled)
#define COMP(v, c) ((c) == 0 ? (v).x : (c) == 1 ? (v).y : (c) == 2 ? (v).z : (v).w)

// ---------------- edge-index dtype detection ----------------
// int64 layout: words are [lo, hi, lo, hi, ...] with hi == 0 (values < 100000).
// int32 layout: odd words are src[1], src[3], ... (random in [0,1e5), ~surely nonzero).
__global__ void detect_kernel(const int* ei32) {
    if (blockIdx.x == 0 && threadIdx.x == 0) {
        int any = 0;
        for (int i = 1; i < 512; i += 2) any |= ei32[i];
        g_i64 = (any == 0) ? 1 : 0;
    }
}

__global__ void zero_deg_kernel() {
    int n = blockIdx.x * blockDim.x + threadIdx.x;
    if (n < N_NODES) g_deg[n] = 0.f;
}

// decode indices to int32, dist per edge, degree per dst node
__global__ void prep_kernel(const void* ei, const float* __restrict__ pos) {
    int e = blockIdx.x * blockDim.x + threadIdx.x;
    if (e >= N_EDGES) return;
    int src, dst;
    if (g_i64) {
        const long long* p = (const long long*)ei;
        src = (int)p[e]; dst = (int)p[N_EDGES + e];
    } else {
        const int* p = (const int*)ei;
        src = p[e]; dst = p[N_EDGES + e];
    }
    g_src[e] = src;
    g_dst[e] = dst;
    float dx = pos[dst * 3 + 0] - pos[src * 3 + 0];
    float dy = pos[dst * 3 + 1] - pos[src * 3 + 1];
    float dz = pos[dst * 3 + 2] - pos[src * 3 + 2];
    g_dist[e] = sqrtf(dx * dx + dy * dy + dz * dz);
    atomicAdd(&g_deg[dst], 1.0f);
}

// ---------------- encoder: x = relu(feat@w1+b1)@w2+b2 ----------------
// feat tile staged through smem with coalesced loads; padded stride 65 for
// conflict-free (tid + k) bank mapping during compute.
__global__ void __launch_bounds__(128) encoder_kernel(
    const float* __restrict__ feat,
    const float* __restrict__ w1, const float* __restrict__ b1,
    const float* __restrict__ w2, const float* __restrict__ b2) {
    __shared__ float  s_feat[128 * 65];
    __shared__ float4 s_w1[64 * 8];
    __shared__ float4 s_w2[32 * 8];
    __shared__ float4 s_b1[8], s_b2[8];
    for (int i = threadIdx.x; i < 512; i += 128) s_w1[i] = ((const float4*)w1)[i];
    for (int i = threadIdx.x; i < 256; i += 128) s_w2[i] = ((const float4*)w2)[i];
    if (threadIdx.x < 8) {
        s_b1[threadIdx.x] = ((const float4*)b1)[threadIdx.x];
        s_b2[threadIdx.x] = ((const float4*)b2)[threadIdx.x];
    }
    int base = blockIdx.x * 128;
    // coalesced tile load: 128 rows x 64 cols
    for (int j = threadIdx.x; j < 128 * 64; j += 128) {
        int r = j >> 6, col = j & 63;
        int nn = base + r;
        s_feat[r * 65 + col] = (nn < N_NODES) ? feat[(size_t)nn * 64 + col] : 0.f;
    }
    __syncthreads();
    int n = base + threadIdx.x;
    if (n >= N_NODES) return;

    const float* frow = &s_feat[threadIdx.x * 65];
    float4 h[8];
#pragma unroll
    for (int i = 0; i < 8; i++) h[i] = s_b1[i];
#pragma unroll 8
    for (int k = 0; k < 64; k++) {
        float f = frow[k];
#pragma unroll
        for (int i = 0; i < 8; i++) h[i] = fma4(f, s_w1[k * 8 + i], h[i]);
    }
#pragma unroll
    for (int i = 0; i < 8; i++) h[i] = relu4(h[i]);

    float4 y[8];
#pragma unroll
    for (int i = 0; i < 8; i++) y[i] = s_b2[i];
#pragma unroll
    for (int k = 0; k < 32; k++) {
        float f = COMP(h[k >> 2], k & 3);
#pragma unroll
        for (int i = 0; i < 8; i++) y[i] = fma4(f, s_w2[k * 8 + i], y[i]);
    }
#pragma unroll
    for (int i = 0; i < 8; i++) g_x[(size_t)n * 8 + i] = y[i];
}

// ---------------- per layer: A = x@w1a, B = x@w1b, zero agg ----------------
__global__ void __launch_bounds__(128) ab_kernel(const float* __restrict__ w1) {
    __shared__ float4 s_wa[32 * 8];
    __shared__ float4 s_wb[32 * 8];
    for (int i = threadIdx.x; i < 256; i += 128) {
        s_wa[i] = ((const float4*)w1)[i];
        s_wb[i] = ((const float4*)(w1 + 1024))[i];
    }
    __syncthreads();
    int n = blockIdx.x * blockDim.x + threadIdx.x;
    if (n >= N_NODES) return;

    float4 xr[8];
#pragma unroll
    for (int i = 0; i < 8; i++) xr[i] = g_x[(size_t)n * 8 + i];

    float4 a[8];
#pragma unroll
    for (int i = 0; i < 8; i++) a[i] = make_float4(0.f, 0.f, 0.f, 0.f);
#pragma unroll
    for (int k = 0; k < 32; k++) {
        float f = COMP(xr[k >> 2], k & 3);
#pragma unroll
        for (int i = 0; i < 8; i++) a[i] = fma4(f, s_wa[k * 8 + i], a[i]);
    }
#pragma unroll
    for (int i = 0; i < 8; i++) g_A[(size_t)n * 8 + i] = a[i];

    float4 b[8];
#pragma unroll
    for (int i = 0; i < 8; i++) b[i] = make_float4(0.f, 0.f, 0.f, 0.f);
#pragma unroll
    for (int k = 0; k < 32; k++) {
        float f = COMP(xr[k >> 2], k & 3);
#pragma unroll
        for (int i = 0; i < 8; i++) b[i] = fma4(f, s_wb[k * 8 + i], b[i]);
    }
    float4 z = make_float4(0.f, 0.f, 0.f, 0.f);
#pragma unroll
    for (int i = 0; i < 8; i++) {
        g_B[(size_t)n * 8 + i] = b[i];
        g_agg[(size_t)n * 8 + i] = z;
    }
}

// ---------------- per layer, per edge (8 lanes/edge):
// agg[dst] += relu(A[dst] + B[src] + d*c + b1)
// lane c in [0,8) owns float4 component c of the 32-wide row.
__global__ void __launch_bounds__(256) edge_kernel(
    const float* __restrict__ w1c, const float* __restrict__ b1) {
    __shared__ float4 s_c[8], s_b[8];
    if (threadIdx.x < 8) {
        s_c[threadIdx.x] = ((const float4*)w1c)[threadIdx.x];
        s_b[threadIdx.x] = ((const float4*)b1)[threadIdx.x];
    }
    __syncthreads();
    int t = blockIdx.x * blockDim.x + threadIdx.x;
    int e = t >> 3;
    if (e >= N_EDGES) return;
    int c = t & 7;

    int src = g_src[e];
    int dst = g_dst[e];
    float d = g_dist[e];

    float4 a = g_A[(size_t)dst * 8 + c];
    float4 b = g_B[(size_t)src * 8 + c];
    float4 h = relu4(fma4(d, s_c[c], add4(add4(a, b), s_b[c])));
    float* outp = (float*)&g_agg[(size_t)dst * 8 + c];
    asm volatile("red.global.add.v4.f32 [%0], {%1, %2, %3, %4};"
                 :: "l"(outp), "f"(h.x), "f"(h.y), "f"(h.z), "f"(h.w)
                 : "memory");
}

// ---------------- per layer, per node: agg=aggH@mw2+deg*mb2; x=relu([x|agg]@uw1+ub1)@uw2+ub2 ----------------
__global__ void __launch_bounds__(128) update_kernel(
    const float* __restrict__ mw2, const float* __restrict__ mb2,
    const float* __restrict__ uw1, const float* __restrict__ ub1,
    const float* __restrict__ uw2, const float* __restrict__ ub2) {
    __shared__ float4 s_mw2[256];
    __shared__ float4 s_u1a[256];
    __shared__ float4 s_u1b[256];
    __shared__ float4 s_uw2[256];
    __shared__ float4 s_mb2[8], s_ub1[8], s_ub2[8];
    for (int i = threadIdx.x; i < 256; i += 128) {
        s_mw2[i] = ((const float4*)mw2)[i];
        s_u1a[i] = ((const float4*)uw1)[i];
        s_u1b[i] = ((const float4*)(uw1 + 1024))[i];
        s_uw2[i] = ((const float4*)uw2)[i];
    }
    if (threadIdx.x < 8) {
        s_mb2[threadIdx.x] = ((const float4*)mb2)[threadIdx.x];
        s_ub1[threadIdx.x] = ((const float4*)ub1)[threadIdx.x];
        s_ub2[threadIdx.x] = ((const float4*)ub2)[threadIdx.x];
    }
    __syncthreads();
    int n = blockIdx.x * blockDim.x + threadIdx.x;
    if (n >= N_NODES) return;

    float deg = g_deg[n];
    float4 ar[8];
#pragma unroll
    for (int i = 0; i < 8; i++) ar[i] = g_agg[(size_t)n * 8 + i];

    // agg = aggH @ mw2 + deg * mb2   (segment_sum of second msg-MLP layer)
    float4 agg[8];
#pragma unroll
    for (int i = 0; i < 8; i++) {
        float4 bb = s_mb2[i];
        agg[i] = make_float4(deg * bb.x, deg * bb.y, deg * bb.z, deg * bb.w);
    }
#pragma unroll
    for (int k = 0; k < 32; k++) {
        float f = COMP(ar[k >> 2], k & 3);
#pragma unroll
        for (int i = 0; i < 8; i++) agg[i] = fma4(f, s_mw2[k * 8 + i], agg[i]);
    }

    float4 xr[8];
#pragma unroll
    for (int i = 0; i < 8; i++) xr[i] = g_x[(size_t)n * 8 + i];

    // u = relu(x @ u1a + agg @ u1b + ub1)
    float4 u[8];
#pragma unroll
    for (int i = 0; i < 8; i++) u[i] = s_ub1[i];
#pragma unroll
    for (int k = 0; k < 32; k++) {
        float f = COMP(xr[k >> 2], k & 3);
#pragma unroll
        for (int i = 0; i < 8; i++) u[i] = fma4(f, s_u1a[k * 8 + i], u[i]);
    }
#pragma unroll
    for (int k = 0; k < 32; k++) {
        float f = COMP(agg[k >> 2], k & 3);
#pragma unroll
        for (int i = 0; i < 8; i++) u[i] = fma4(f, s_u1b[k * 8 + i], u[i]);
    }
#pragma unroll
    for (int i = 0; i < 8; i++) u[i] = relu4(u[i]);

    // x = u @ uw2 + ub2
    float4 y[8];
#pragma unroll
    for (int i = 0; i < 8; i++) y[i] = s_ub2[i];
#pragma unroll
    for (int k = 0; k < 32; k++) {
        float f = COMP(u[k >> 2], k & 3);
#pragma unroll
        for (int i = 0; i < 8; i++) y[i] = fma4(f, s_uw2[k * 8 + i], y[i]);
    }
#pragma unroll
    for (int i = 0; i < 8; i++) g_x[(size_t)n * 8 + i] = y[i];
}

// ---------------- output: out = x @ out_w + out_b ----------------
__global__ void __launch_bounds__(128) out_kernel(
    const float* __restrict__ ow, const float* __restrict__ ob, float* __restrict__ out) {
    __shared__ float4 s_w[256];
    __shared__ float4 s_b[8];
    for (int i = threadIdx.x; i < 256; i += 128) s_w[i] = ((const float4*)ow)[i];
    if (threadIdx.x < 8) s_b[threadIdx.x] = ((const float4*)ob)[threadIdx.x];
    __syncthreads();
    int n = blockIdx.x * blockDim.x + threadIdx.x;
    if (n >= N_NODES) return;

    float4 xr[8];
#pragma unroll
    for (int i = 0; i < 8; i++) xr[i] = g_x[(size_t)n * 8 + i];
    float4 y[8];
#pragma unroll
    for (int i = 0; i < 8; i++) y[i] = s_b[i];
#pragma unroll
    for (int k = 0; k < 32; k++) {
        float f = COMP(xr[k >> 2], k & 3);
#pragma unroll
        for (int i = 0; i < 8; i++) y[i] = fma4(f, s_w[k * 8 + i], y[i]);
    }
    float4* orow = (float4*)(out + (size_t)n * 32);
#pragma unroll
    for (int i = 0; i < 8; i++) orow[i] = y[i];
}

// ---------------- launch ----------------
extern "C" void kernel_launch(void* const* d_in, const int* in_sizes, int n_in,
                              void* d_out, int out_size) {
    const float* node_feat = (const float*)d_in[0];
    const float* pos       = (const float*)d_in[1];
    const void*  ei        = d_in[2];
    const float* enc_w1    = (const float*)d_in[3];
    const float* enc_b1    = (const float*)d_in[4];
    const float* enc_w2    = (const float*)d_in[5];
    const float* enc_b2    = (const float*)d_in[6];
    const float* msg_w1    = (const float*)d_in[7];   // [3, 65, 32]
    const float* msg_b1    = (const float*)d_in[8];   // [3, 32]
    const float* msg_w2    = (const float*)d_in[9];   // [3, 32, 32]
    const float* msg_b2    = (const float*)d_in[10];  // [3, 32]
    const float* upd_w1    = (const float*)d_in[11];  // [3, 64, 32]
    const float* upd_b1    = (const float*)d_in[12];
    const float* upd_w2    = (const float*)d_in[13];
    const float* upd_b2    = (const float*)d_in[14];
    const float* out_w     = (const float*)d_in[15];
    const float* out_b     = (const float*)d_in[16];
    float* out = (float*)d_out;

    const int NODE_BLOCKS = (N_NODES + 127) / 128;
    const int EDGE_BLOCKS = (N_EDGES + 255) / 256;
    const long long ET = (long long)N_EDGES * 8;
    const int EDGE8_BLOCKS = (int)((ET + 255) / 256);

    detect_kernel<<<1, 32>>>((const int*)ei);
    zero_deg_kernel<<<(N_NODES + 255) / 256, 256>>>();
    prep_kernel<<<EDGE_BLOCKS, 256>>>(ei, pos);
    encoder_kernel<<<NODE_BLOCKS, 128>>>(node_feat, enc_w1, enc_b1, enc_w2, enc_b2);

    for (int l = 0; l < 3; l++) {
        const float* w1  = msg_w1 + (size_t)l * 65 * 32;
        ab_kernel<<<NODE_BLOCKS, 128>>>(w1);
        edge_kernel<<<EDGE8_BLOCKS, 256>>>(w1 + 64 * 32, msg_b1 + (size_t)l * 32);
        update_kernel<<<NODE_BLOCKS, 128>>>(
            msg_w2 + (size_t)l * 32 * 32, msg_b2 + (size_t)l * 32,
            upd_w1 + (size_t)l * 64 * 32, upd_b1 + (size_t)l * 32,
            upd_w2 + (size_t)l * 32 * 32, upd_b2 + (size_t)l * 32);
    }
    out_kernel<<<NODE_BLOCKS, 128>>>(out_w, out_b, out);
}

// round 3
// speedup vs baseline: 1.8866x; 1.1156x over previous
#include <cuda_runtime.h>
#include <math.h>

#define N_NODES 100000
#define N_EDGES 1600000
#define HID 32
#define N_SBLOCKS ((N_NODES + 511) / 512)   // scan blocks (196)

// ---------------- device scratch (no allocs allowed) ----------------
__device__ int    g_i64;                    // 1 if edge_index is int64, 0 if int32
__device__ float4 g_x  [N_NODES * 8];       // node embedding x   [N,32]
__device__ float4 g_A  [N_NODES * 8];       // x @ msg_w1[0:32]   [N,32]
__device__ float4 g_B  [N_NODES * 8];       // x @ msg_w1[32:64]  [N,32]
__device__ float4 g_agg[N_NODES * 8];       // sum of relu(h) per dst [N,32]
__device__ int    g_src [N_EDGES];          // decoded int32 edge index
__device__ int    g_dst [N_EDGES];
__device__ int    g_esrc[N_EDGES];          // CSR: src sorted by dst
__device__ float  g_edist[N_EDGES];         // CSR: dist sorted by dst
__device__ int    g_hist[N_NODES];          // in-degree
__device__ int    g_off [N_NODES];          // exclusive prefix of hist
__device__ int    g_cur [N_NODES];          // scatter cursor
__device__ int    g_bsum[N_SBLOCKS];

// ---------------- small helpers ----------------
__device__ __forceinline__ float4 fma4(float f, float4 w, float4 a) {
    a.x = fmaf(f, w.x, a.x); a.y = fmaf(f, w.y, a.y);
    a.z = fmaf(f, w.z, a.z); a.w = fmaf(f, w.w, a.w);
    return a;
}
__device__ __forceinline__ float4 add4(float4 a, float4 b) {
    a.x += b.x; a.y += b.y; a.z += b.z; a.w += b.w; return a;
}
__device__ __forceinline__ float4 relu4(float4 v) {
    v.x = fmaxf(v.x, 0.f); v.y = fmaxf(v.y, 0.f);
    v.z = fmaxf(v.z, 0.f); v.w = fmaxf(v.w, 0.f); return v;
}
#define COMP(v, c) ((c) == 0 ? (v).x : (c) == 1 ? (v).y : (c) == 2 ? (v).z : (v).w)

// ---------------- edge-index dtype detection ----------------
__global__ void detect_kernel(const int* ei32) {
    if (blockIdx.x == 0 && threadIdx.x == 0) {
        int any = 0;
        for (int i = 1; i < 512; i += 2) any |= ei32[i];
        g_i64 = (any == 0) ? 1 : 0;
    }
}

__global__ void zero_hist_kernel() {
    int n = blockIdx.x * blockDim.x + threadIdx.x;
    if (n < N_NODES) g_hist[n] = 0;
}

// decode indices to int32 + in-degree histogram
__global__ void decode_kernel(const void* ei) {
    int e = blockIdx.x * blockDim.x + threadIdx.x;
    if (e >= N_EDGES) return;
    int src, dst;
    if (g_i64) {
        const long long* p = (const long long*)ei;
        src = (int)p[e]; dst = (int)p[N_EDGES + e];
    } else {
        const int* p = (const int*)ei;
        src = p[e]; dst = p[N_EDGES + e];
    }
    g_src[e] = src;
    g_dst[e] = dst;
    atomicAdd(&g_hist[dst], 1);
}

// ---------------- 3-kernel exclusive scan of g_hist -> g_off ----------------
__global__ void __launch_bounds__(512) scan1_kernel() {
    __shared__ int s[512];
    int tid = threadIdx.x;
    int i = blockIdx.x * 512 + tid;
    int v = (i < N_NODES) ? g_hist[i] : 0;
    s[tid] = v;
    __syncthreads();
#pragma unroll
    for (int off = 1; off < 512; off <<= 1) {
        int t = (tid >= off) ? s[tid - off] : 0;
        __syncthreads();
        s[tid] += t;
        __syncthreads();
    }
    if (i < N_NODES) g_off[i] = s[tid] - v;   // exclusive
    if (tid == 511) g_bsum[blockIdx.x] = s[511];
}

__global__ void __launch_bounds__(256) scan2_kernel() {
    __shared__ int s[256];
    int tid = threadIdx.x;
    int v = (tid < N_SBLOCKS) ? g_bsum[tid] : 0;
    s[tid] = v;
    __syncthreads();
#pragma unroll
    for (int off = 1; off < 256; off <<= 1) {
        int t = (tid >= off) ? s[tid - off] : 0;
        __syncthreads();
        s[tid] += t;
        __syncthreads();
    }
    if (tid < N_SBLOCKS) g_bsum[tid] = s[tid] - v;  // exclusive
}

__global__ void __launch_bounds__(512) scan3_kernel() {
    int i = blockIdx.x * 512 + threadIdx.x;
    if (i >= N_NODES) return;
    int off = g_off[i] + g_bsum[i >> 9];
    g_off[i] = off;
    g_cur[i] = off;
}

// scatter edges into CSR order (by dst); computes dist here
__global__ void scatter_kernel(const float* __restrict__ pos) {
    int e = blockIdx.x * blockDim.x + threadIdx.x;
    if (e >= N_EDGES) return;
    int src = g_src[e];
    int dst = g_dst[e];
    float dx = pos[dst * 3 + 0] - pos[src * 3 + 0];
    float dy = pos[dst * 3 + 1] - pos[src * 3 + 1];
    float dz = pos[dst * 3 + 2] - pos[src * 3 + 2];
    float dist = sqrtf(dx * dx + dy * dy + dz * dz);
    int p = atomicAdd(&g_cur[dst], 1);
    g_esrc[p] = src;
    g_edist[p] = dist;
}

// ---------------- encoder: x = relu(feat@w1+b1)@w2+b2 ----------------
__global__ void __launch_bounds__(128) encoder_kernel(
    const float* __restrict__ feat,
    const float* __restrict__ w1, const float* __restrict__ b1,
    const float* __restrict__ w2, const float* __restrict__ b2) {
    __shared__ float  s_feat[128 * 65];
    __shared__ float4 s_w1[64 * 8];
    __shared__ float4 s_w2[32 * 8];
    __shared__ float4 s_b1[8], s_b2[8];
    for (int i = threadIdx.x; i < 512; i += 128) s_w1[i] = ((const float4*)w1)[i];
    for (int i = threadIdx.x; i < 256; i += 128) s_w2[i] = ((const float4*)w2)[i];
    if (threadIdx.x < 8) {
        s_b1[threadIdx.x] = ((const float4*)b1)[threadIdx.x];
        s_b2[threadIdx.x] = ((const float4*)b2)[threadIdx.x];
    }
    int base = blockIdx.x * 128;
    for (int j = threadIdx.x; j < 128 * 64; j += 128) {
        int r = j >> 6, col = j & 63;
        int nn = base + r;
        s_feat[r * 65 + col] = (nn < N_NODES) ? feat[(size_t)nn * 64 + col] : 0.f;
    }
    __syncthreads();
    int n = base + threadIdx.x;
    if (n >= N_NODES) return;

    const float* frow = &s_feat[threadIdx.x * 65];
    float4 h[8];
#pragma unroll
    for (int i = 0; i < 8; i++) h[i] = s_b1[i];
#pragma unroll 8
    for (int k = 0; k < 64; k++) {
        float f = frow[k];
#pragma unroll
        for (int i = 0; i < 8; i++) h[i] = fma4(f, s_w1[k * 8 + i], h[i]);
    }
#pragma unroll
    for (int i = 0; i < 8; i++) h[i] = relu4(h[i]);

    float4 y[8];
#pragma unroll
    for (int i = 0; i < 8; i++) y[i] = s_b2[i];
#pragma unroll
    for (int k = 0; k < 32; k++) {
        float f = COMP(h[k >> 2], k & 3);
#pragma unroll
        for (int i = 0; i < 8; i++) y[i] = fma4(f, s_w2[k * 8 + i], y[i]);
    }
#pragma unroll
    for (int i = 0; i < 8; i++) g_x[(size_t)n * 8 + i] = y[i];
}

// ---------------- per layer: A = x@w1a, B = x@w1b ----------------
__global__ void __launch_bounds__(128) ab_kernel(const float* __restrict__ w1) {
    __shared__ float4 s_wa[32 * 8];
    __shared__ float4 s_wb[32 * 8];
    for (int i = threadIdx.x; i < 256; i += 128) {
        s_wa[i] = ((const float4*)w1)[i];
        s_wb[i] = ((const float4*)(w1 + 1024))[i];
    }
    __syncthreads();
    int n = blockIdx.x * blockDim.x + threadIdx.x;
    if (n >= N_NODES) return;

    float4 xr[8];
#pragma unroll
    for (int i = 0; i < 8; i++) xr[i] = g_x[(size_t)n * 8 + i];

    float4 a[8];
#pragma unroll
    for (int i = 0; i < 8; i++) a[i] = make_float4(0.f, 0.f, 0.f, 0.f);
#pragma unroll
    for (int k = 0; k < 32; k++) {
        float f = COMP(xr[k >> 2], k & 3);
#pragma unroll
        for (int i = 0; i < 8; i++) a[i] = fma4(f, s_wa[k * 8 + i], a[i]);
    }
#pragma unroll
    for (int i = 0; i < 8; i++) g_A[(size_t)n * 8 + i] = a[i];

    float4 b[8];
#pragma unroll
    for (int i = 0; i < 8; i++) b[i] = make_float4(0.f, 0.f, 0.f, 0.f);
#pragma unroll
    for (int k = 0; k < 32; k++) {
        float f = COMP(xr[k >> 2], k & 3);
#pragma unroll
        for (int i = 0; i < 8; i++) b[i] = fma4(f, s_wb[k * 8 + i], b[i]);
    }
#pragma unroll
    for (int i = 0; i < 8; i++) g_B[(size_t)n * 8 + i] = b[i];
}

// ---------------- per layer, warp per dst node over CSR edge list:
// agg[n] = sum_e relu(A[n] + B[src_e] + d_e*c + b1)    -- NO atomics
// lane layout: c = lane&7 owns float4 component c; slot = lane>>3 strides edges by 4
__global__ void __launch_bounds__(256) agg_kernel(
    const float* __restrict__ w1c, const float* __restrict__ b1) {
    __shared__ float4 s_c[8], s_b[8];
    if (threadIdx.x < 8) {
        s_c[threadIdx.x] = ((const float4*)w1c)[threadIdx.x];
        s_b[threadIdx.x] = ((const float4*)b1)[threadIdx.x];
    }
    __syncthreads();
    int n = (blockIdx.x * 256 + threadIdx.x) >> 5;
    if (n >= N_NODES) return;
    int lane = threadIdx.x & 31;
    int c = lane & 7;
    int slot = lane >> 3;

    int start = g_off[n];
    int end = start + g_hist[n];

    float4 ab = add4(g_A[(size_t)n * 8 + c], s_b[c]);   // A[n] + b1, reused per edge
    float4 cv = s_c[c];
    float4 acc = make_float4(0.f, 0.f, 0.f, 0.f);

    for (int i = start + slot; i < end; i += 4) {
        int src = g_esrc[i];
        float d = g_edist[i];
        float4 b = g_B[(size_t)src * 8 + c];
        acc = add4(acc, relu4(fma4(d, cv, add4(ab, b))));
    }
    // reduce across the 4 slots (lane bits 3,4)
#pragma unroll
    for (int m = 8; m <= 16; m <<= 1) {
        acc.x += __shfl_xor_sync(0xffffffffu, acc.x, m);
        acc.y += __shfl_xor_sync(0xffffffffu, acc.y, m);
        acc.z += __shfl_xor_sync(0xffffffffu, acc.z, m);
        acc.w += __shfl_xor_sync(0xffffffffu, acc.w, m);
    }
    if (lane < 8) g_agg[(size_t)n * 8 + lane] = acc;
}

// ---------------- per layer, per node: agg=aggH@mw2+deg*mb2; x=relu([x|agg]@uw1+ub1)@uw2+ub2 ----------------
__global__ void __launch_bounds__(128) update_kernel(
    const float* __restrict__ mw2, const float* __restrict__ mb2,
    const float* __restrict__ uw1, const float* __restrict__ ub1,
    const float* __restrict__ uw2, const float* __restrict__ ub2) {
    __shared__ float4 s_mw2[256];
    __shared__ float4 s_u1a[256];
    __shared__ float4 s_u1b[256];
    __shared__ float4 s_uw2[256];
    __shared__ float4 s_mb2[8], s_ub1[8], s_ub2[8];
    for (int i = threadIdx.x; i < 256; i += 128) {
        s_mw2[i] = ((const float4*)mw2)[i];
        s_u1a[i] = ((const float4*)uw1)[i];
        s_u1b[i] = ((const float4*)(uw1 + 1024))[i];
        s_uw2[i] = ((const float4*)uw2)[i];
    }
    if (threadIdx.x < 8) {
        s_mb2[threadIdx.x] = ((const float4*)mb2)[threadIdx.x];
        s_ub1[threadIdx.x] = ((const float4*)ub1)[threadIdx.x];
        s_ub2[threadIdx.x] = ((const float4*)ub2)[threadIdx.x];
    }
    __syncthreads();
    int n = blockIdx.x * blockDim.x + threadIdx.x;
    if (n >= N_NODES) return;

    float deg = (float)g_hist[n];
    float4 ar[8];
#pragma unroll
    for (int i = 0; i < 8; i++) ar[i] = g_agg[(size_t)n * 8 + i];

    float4 agg[8];
#pragma unroll
    for (int i = 0; i < 8; i++) {
        float4 bb = s_mb2[i];
        agg[i] = make_float4(deg * bb.x, deg * bb.y, deg * bb.z, deg * bb.w);
    }
#pragma unroll
    for (int k = 0; k < 32; k++) {
        float f = COMP(ar[k >> 2], k & 3);
#pragma unroll
        for (int i = 0; i < 8; i++) agg[i] = fma4(f, s_mw2[k * 8 + i], agg[i]);
    }

    float4 xr[8];
#pragma unroll
    for (int i = 0; i < 8; i++) xr[i] = g_x[(size_t)n * 8 + i];

    float4 u[8];
#pragma unroll
    for (int i = 0; i < 8; i++) u[i] = s_ub1[i];
#pragma unroll
    for (int k = 0; k < 32; k++) {
        float f = COMP(xr[k >> 2], k & 3);
#pragma unroll
        for (int i = 0; i < 8; i++) u[i] = fma4(f, s_u1a[k * 8 + i], u[i]);
    }
#pragma unroll
    for (int k = 0; k < 32; k++) {
        float f = COMP(agg[k >> 2], k & 3);
#pragma unroll
        for (int i = 0; i < 8; i++) u[i] = fma4(f, s_u1b[k * 8 + i], u[i]);
    }
#pragma unroll
    for (int i = 0; i < 8; i++) u[i] = relu4(u[i]);

    float4 y[8];
#pragma unroll
    for (int i = 0; i < 8; i++) y[i] = s_ub2[i];
#pragma unroll
    for (int k = 0; k < 32; k++) {
        float f = COMP(u[k >> 2], k & 3);
#pragma unroll
        for (int i = 0; i < 8; i++) y[i] = fma4(f, s_uw2[k * 8 + i], y[i]);
    }
#pragma unroll
    for (int i = 0; i < 8; i++) g_x[(size_t)n * 8 + i] = y[i];
}

// ---------------- output: out = x @ out_w + out_b ----------------
__global__ void __launch_bounds__(128) out_kernel(
    const float* __restrict__ ow, const float* __restrict__ ob, float* __restrict__ out) {
    __shared__ float4 s_w[256];
    __shared__ float4 s_b[8];
    for (int i = threadIdx.x; i < 256; i += 128) s_w[i] = ((const float4*)ow)[i];
    if (threadIdx.x < 8) s_b[threadIdx.x] = ((const float4*)ob)[threadIdx.x];
    __syncthreads();
    int n = blockIdx.x * blockDim.x + threadIdx.x;
    if (n >= N_NODES) return;

    float4 xr[8];
#pragma unroll
    for (int i = 0; i < 8; i++) xr[i] = g_x[(size_t)n * 8 + i];
    float4 y[8];
#pragma unroll
    for (int i = 0; i < 8; i++) y[i] = s_b[i];
#pragma unroll
    for (int k = 0; k < 32; k++) {
        float f = COMP(xr[k >> 2], k & 3);
#pragma unroll
        for (int i = 0; i < 8; i++) y[i] = fma4(f, s_w[k * 8 + i], y[i]);
    }
    float4* orow = (float4*)(out + (size_t)n * 32);
#pragma unroll
    for (int i = 0; i < 8; i++) orow[i] = y[i];
}

// ---------------- launch ----------------
extern "C" void kernel_launch(void* const* d_in, const int* in_sizes, int n_in,
                              void* d_out, int out_size) {
    const float* node_feat = (const float*)d_in[0];
    const float* pos       = (const float*)d_in[1];
    const void*  ei        = d_in[2];
    const float* enc_w1    = (const float*)d_in[3];
    const float* enc_b1    = (const float*)d_in[4];
    const float* enc_w2    = (const float*)d_in[5];
    const float* enc_b2    = (const float*)d_in[6];
    const float* msg_w1    = (const float*)d_in[7];   // [3, 65, 32]
    const float* msg_b1    = (const float*)d_in[8];   // [3, 32]
    const float* msg_w2    = (const float*)d_in[9];   // [3, 32, 32]
    const float* msg_b2    = (const float*)d_in[10];  // [3, 32]
    const float* upd_w1    = (const float*)d_in[11];  // [3, 64, 32]
    const float* upd_b1    = (const float*)d_in[12];
    const float* upd_w2    = (const float*)d_in[13];
    const float* upd_b2    = (const float*)d_in[14];
    const float* out_w     = (const float*)d_in[15];
    const float* out_b     = (const float*)d_in[16];
    float* out = (float*)d_out;

    const int NODE_BLOCKS = (N_NODES + 127) / 128;
    const int EDGE_BLOCKS = (N_EDGES + 255) / 256;
    const int AGG_BLOCKS  = (N_NODES * 32 + 255) / 256;

    detect_kernel<<<1, 32>>>((const int*)ei);
    zero_hist_kernel<<<(N_NODES + 255) / 256, 256>>>();
    decode_kernel<<<EDGE_BLOCKS, 256>>>(ei);
    scan1_kernel<<<N_SBLOCKS, 512>>>();
    scan2_kernel<<<1, 256>>>();
    scan3_kernel<<<N_SBLOCKS, 512>>>();
    scatter_kernel<<<EDGE_BLOCKS, 256>>>(pos);
    encoder_kernel<<<NODE_BLOCKS, 128>>>(node_feat, enc_w1, enc_b1, enc_w2, enc_b2);

    for (int l = 0; l < 3; l++) {
        const float* w1 = msg_w1 + (size_t)l * 65 * 32;
        ab_kernel<<<NODE_BLOCKS, 128>>>(w1);
        agg_kernel<<<AGG_BLOCKS, 256>>>(w1 + 64 * 32, msg_b1 + (size_t)l * 32);
        update_kernel<<<NODE_BLOCKS, 128>>>(
            msg_w2 + (size_t)l * 32 * 32, msg_b2 + (size_t)l * 32,
            upd_w1 + (size_t)l * 64 * 32, upd_b1 + (size_t)l * 32,
            upd_w2 + (size_t)l * 32 * 32, upd_b2 + (size_t)l * 32);
    }
    out_kernel<<<NODE_BLOCKS, 128>>>(out_w, out_b, out);
}

// round 5
// speedup vs baseline: 1.9247x; 1.0202x over previous
#include <cuda_runtime.h>
#include <math.h>

#define N_NODES 100000
#define N_EDGES 1600000
#define HID 32
#define N_SBLOCKS ((N_NODES + 511) / 512)   // scan blocks (196)

// ---------------- device scratch (no allocs allowed) ----------------
__device__ int    g_i64;
__device__ float4 g_x  [N_NODES * 8];       // node embedding x   [N,32]
__device__ float4 g_A  [N_NODES * 8];       // x @ msg_w1[0:32]   [N,32]
__device__ float4 g_B  [N_NODES * 8];       // x @ msg_w1[32:64]  [N,32]
__device__ float4 g_agg[N_NODES * 8];       // sum of relu(h) per dst [N,32]
__device__ int    g_src [N_EDGES];
__device__ int    g_dst [N_EDGES];
__device__ int2   g_epack[N_EDGES];         // CSR by dst: (src, dist bits)
__device__ int    g_hist[N_NODES];          // in-degree
__device__ int    g_off [N_NODES];          // exclusive prefix of hist
__device__ int    g_cur [N_NODES];
__device__ int    g_bsum[N_SBLOCKS];

// ---------------- small helpers ----------------
__device__ __forceinline__ float4 fma4(float f, float4 w, float4 a) {
    a.x = fmaf(f, w.x, a.x); a.y = fmaf(f, w.y, a.y);
    a.z = fmaf(f, w.z, a.z); a.w = fmaf(f, w.w, a.w);
    return a;
}
__device__ __forceinline__ float4 add4(float4 a, float4 b) {
    a.x += b.x; a.y += b.y; a.z += b.z; a.w += b.w; return a;
}
__device__ __forceinline__ float4 relu4(float4 v) {
    v.x = fmaxf(v.x, 0.f); v.y = fmaxf(v.y, 0.f);
    v.z = fmaxf(v.z, 0.f); v.w = fmaxf(v.w, 0.f); return v;
}
#define COMP(v, c) ((c) == 0 ? (v).x : (c) == 1 ? (v).y : (c) == 2 ? (v).z : (v).w)

// ---------------- edge-index dtype detection ----------------
__global__ void detect_kernel(const int* ei32) {
    if (blockIdx.x == 0 && threadIdx.x == 0) {
        int any = 0;
        for (int i = 1; i < 512; i += 2) any |= ei32[i];
        g_i64 = (any == 0) ? 1 : 0;
    }
}

__global__ void zero_hist_kernel() {
    int n = blockIdx.x * blockDim.x + threadIdx.x;
    if (n < N_NODES) g_hist[n] = 0;
}

__global__ void decode_kernel(const void* ei) {
    int e = blockIdx.x * blockDim.x + threadIdx.x;
    if (e >= N_EDGES) return;
    int src, dst;
    if (g_i64) {
        const long long* p = (const long long*)ei;
        src = (int)p[e]; dst = (int)p[N_EDGES + e];
    } else {
        const int* p = (const int*)ei;
        src = p[e]; dst = p[N_EDGES + e];
    }
    g_src[e] = src;
    g_dst[e] = dst;
    atomicAdd(&g_hist[dst], 1);
}

// ---------------- 3-kernel exclusive scan of g_hist -> g_off ----------------
__global__ void __launch_bounds__(512) scan1_kernel() {
    __shared__ int s[512];
    int tid = threadIdx.x;
    int i = blockIdx.x * 512 + tid;
    int v = (i < N_NODES) ? g_hist[i] : 0;
    s[tid] = v;
    __syncthreads();
#pragma unroll
    for (int off = 1; off < 512; off <<= 1) {
        int t = (tid >= off) ? s[tid - off] : 0;
        __syncthreads();
        s[tid] += t;
        __syncthreads();
    }
    if (i < N_NODES) g_off[i] = s[tid] - v;
    if (tid == 511) g_bsum[blockIdx.x] = s[511];
}

__global__ void __launch_bounds__(256) scan2_kernel() {
    __shared__ int s[256];
    int tid = threadIdx.x;
    int v = (tid < N_SBLOCKS) ? g_bsum[tid] : 0;
    s[tid] = v;
    __syncthreads();
#pragma unroll
    for (int off = 1; off < 256; off <<= 1) {
        int t = (tid >= off) ? s[tid - off] : 0;
        __syncthreads();
        s[tid] += t;
        __syncthreads();
    }
    if (tid < N_SBLOCKS) g_bsum[tid] = s[tid] - v;
}

__global__ void __launch_bounds__(512) scan3_kernel() {
    int i = blockIdx.x * 512 + threadIdx.x;
    if (i >= N_NODES) return;
    int off = g_off[i] + g_bsum[i >> 9];
    g_off[i] = off;
    g_cur[i] = off;
}

// scatter edges into CSR order (by dst); packs (src, dist)
__global__ void scatter_kernel(const float* __restrict__ pos) {
    int e = blockIdx.x * blockDim.x + threadIdx.x;
    if (e >= N_EDGES) return;
    int src = g_src[e];
    int dst = g_dst[e];
    float dx = pos[dst * 3 + 0] - pos[src * 3 + 0];
    float dy = pos[dst * 3 + 1] - pos[src * 3 + 1];
    float dz = pos[dst * 3 + 2] - pos[src * 3 + 2];
    float dist = sqrtf(dx * dx + dy * dy + dz * dz);
    int p = atomicAdd(&g_cur[dst], 1);
    g_epack[p] = make_int2(src, __float_as_int(dist));
}

// ---------------- encoder (fused): x = relu(feat@w1+b1)@w2+b2; A=x@wa; B=x@wb ----------------
// split-K feat tile: 128 rows x 33 (padded), two halves, reloaded
__global__ void __launch_bounds__(128) encoder_kernel(
    const float* __restrict__ feat,
    const float* __restrict__ w1, const float* __restrict__ b1,
    const float* __restrict__ w2, const float* __restrict__ b2,
    const float* __restrict__ wa /* msg_w1[0], rows 0..63 */) {
    __shared__ float  s_feat[128 * 33];
    __shared__ float4 s_w1[64 * 8];
    __shared__ float4 s_w2[32 * 8];
    __shared__ float4 s_wa[32 * 8];
    __shared__ float4 s_wb[32 * 8];
    __shared__ float4 s_b1[8], s_b2[8];
    for (int i = threadIdx.x; i < 512; i += 128) s_w1[i] = ((const float4*)w1)[i];
    for (int i = threadIdx.x; i < 256; i += 128) {
        s_w2[i] = ((const float4*)w2)[i];
        s_wa[i] = ((const float4*)wa)[i];
        s_wb[i] = ((const float4*)(wa + 1024))[i];
    }
    if (threadIdx.x < 8) {
        s_b1[threadIdx.x] = ((const float4*)b1)[threadIdx.x];
        s_b2[threadIdx.x] = ((const float4*)b2)[threadIdx.x];
    }
    __syncthreads();   // <<< bias/weights visible before ANY thread reads them
    int base = blockIdx.x * 128;
    int n = base + threadIdx.x;
    bool act = (n < N_NODES);

    float4 h[8];
#pragma unroll
    for (int i = 0; i < 8; i++) h[i] = s_b1[i];

#pragma unroll
    for (int half = 0; half < 2; half++) {
        for (int j = threadIdx.x; j < 128 * 32; j += 128) {
            int r = j >> 5, col = j & 31;
            int nn = base + r;
            s_feat[r * 33 + col] =
                (nn < N_NODES) ? feat[(size_t)nn * 64 + half * 32 + col] : 0.f;
        }
        __syncthreads();
        const float* frow = &s_feat[threadIdx.x * 33];
#pragma unroll 8
        for (int k = 0; k < 32; k++) {
            float f = frow[k];
            int kk = half * 32 + k;
#pragma unroll
            for (int i = 0; i < 8; i++) h[i] = fma4(f, s_w1[kk * 8 + i], h[i]);
        }
        __syncthreads();   // protect s_feat before refill (and harmless on last iter)
    }
#pragma unroll
    for (int i = 0; i < 8; i++) h[i] = relu4(h[i]);

    float4 y[8];
#pragma unroll
    for (int i = 0; i < 8; i++) y[i] = s_b2[i];
#pragma unroll
    for (int k = 0; k < 32; k++) {
        float f = COMP(h[k >> 2], k & 3);
#pragma unroll
        for (int i = 0; i < 8; i++) y[i] = fma4(f, s_w2[k * 8 + i], y[i]);
    }

    // A = y@wa, B = y@wb
    float4 a[8], b[8];
#pragma unroll
    for (int i = 0; i < 8; i++) { a[i] = make_float4(0,0,0,0); b[i] = make_float4(0,0,0,0); }
#pragma unroll
    for (int k = 0; k < 32; k++) {
        float f = COMP(y[k >> 2], k & 3);
#pragma unroll
        for (int i = 0; i < 8; i++) {
            a[i] = fma4(f, s_wa[k * 8 + i], a[i]);
            b[i] = fma4(f, s_wb[k * 8 + i], b[i]);
        }
    }
    if (act) {
#pragma unroll
        for (int i = 0; i < 8; i++) {
            g_x[(size_t)n * 8 + i] = y[i];
            g_A[(size_t)n * 8 + i] = a[i];
            g_B[(size_t)n * 8 + i] = b[i];
        }
    }
}

// ---------------- per layer, warp per dst node over CSR edge list (no smem) ----------------
// agg[n] = sum_e relu(A[n] + B[src_e] + d_e*c + b1)
__global__ void __launch_bounds__(128) agg_kernel(
    const float* __restrict__ w1c, const float* __restrict__ b1) {
    int n = (blockIdx.x * 128 + threadIdx.x) >> 5;
    if (n >= N_NODES) return;
    int lane = threadIdx.x & 31;
    int c = lane & 7;
    int slot = lane >> 3;

    float4 cv = __ldg(((const float4*)w1c) + c);
    float4 bb = __ldg(((const float4*)b1) + c);

    int start = __ldg(&g_off[n]);
    int end = start + __ldg(&g_hist[n]);

    float4 ab = add4(g_A[(size_t)n * 8 + c], bb);
    float4 acc = make_float4(0.f, 0.f, 0.f, 0.f);

    int i = start + slot;
    bool valid = (i < end);
    int2 sd = valid ? __ldg(&g_epack[i]) : make_int2(0, 0);
    while (valid) {
        int nxt = i + 4;
        bool nv = (nxt < end);
        int2 sd2 = nv ? __ldg(&g_epack[nxt]) : make_int2(0, 0);
        int src = sd.x;
        float d = __int_as_float(sd.y);
        float4 b = g_B[(size_t)src * 8 + c];
        acc = add4(acc, relu4(fma4(d, cv, add4(ab, b))));
        i = nxt; sd = sd2; valid = nv;
    }
#pragma unroll
    for (int m = 8; m <= 16; m <<= 1) {
        acc.x += __shfl_xor_sync(0xffffffffu, acc.x, m);
        acc.y += __shfl_xor_sync(0xffffffffu, acc.y, m);
        acc.z += __shfl_xor_sync(0xffffffffu, acc.z, m);
        acc.w += __shfl_xor_sync(0xffffffffu, acc.w, m);
    }
    if (lane < 8) g_agg[(size_t)n * 8 + lane] = acc;
}

// ---------------- per layer (fused): update + (next A/B  |  final output) ----------------
__global__ void __launch_bounds__(128) update_kernel(
    const float* __restrict__ mw2, const float* __restrict__ mb2,
    const float* __restrict__ uw1, const float* __restrict__ ub1,
    const float* __restrict__ uw2, const float* __restrict__ ub2,
    const float* __restrict__ e1p, const float* __restrict__ e2p,
    const float* __restrict__ ebp, float* __restrict__ outp, int last) {
    __shared__ float4 s_mw2[256];
    __shared__ float4 s_u1a[256];
    __shared__ float4 s_u1b[256];
    __shared__ float4 s_uw2[256];
    __shared__ float4 s_e1[256];
    __shared__ float4 s_e2[256];
    __shared__ float4 s_mb2[8], s_ub1[8], s_ub2[8], s_eb[8];
    for (int i = threadIdx.x; i < 256; i += 128) {
        s_mw2[i] = ((const float4*)mw2)[i];
        s_u1a[i] = ((const float4*)uw1)[i];
        s_u1b[i] = ((const float4*)(uw1 + 1024))[i];
        s_uw2[i] = ((const float4*)uw2)[i];
        s_e1[i]  = ((const float4*)e1p)[i];
        s_e2[i]  = ((const float4*)e2p)[i];
    }
    if (threadIdx.x < 8) {
        s_mb2[threadIdx.x] = ((const float4*)mb2)[threadIdx.x];
        s_ub1[threadIdx.x] = ((const float4*)ub1)[threadIdx.x];
        s_ub2[threadIdx.x] = ((const float4*)ub2)[threadIdx.x];
        s_eb[threadIdx.x]  = ((const float4*)ebp)[threadIdx.x];
    }
    __syncthreads();
    int n = blockIdx.x * blockDim.x + threadIdx.x;
    if (n >= N_NODES) return;

    float deg = (float)g_hist[n];
    float4 ar[8];
#pragma unroll
    for (int i = 0; i < 8; i++) ar[i] = g_agg[(size_t)n * 8 + i];

    // agg = aggH @ mw2 + deg * mb2
    float4 agg[8];
#pragma unroll
    for (int i = 0; i < 8; i++) {
        float4 bbv = s_mb2[i];
        agg[i] = make_float4(deg * bbv.x, deg * bbv.y, deg * bbv.z, deg * bbv.w);
    }
#pragma unroll
    for (int k = 0; k < 32; k++) {
        float f = COMP(ar[k >> 2], k & 3);
#pragma unroll
        for (int i = 0; i < 8; i++) agg[i] = fma4(f, s_mw2[k * 8 + i], agg[i]);
    }

    float4 xr[8];
#pragma unroll
    for (int i = 0; i < 8; i++) xr[i] = g_x[(size_t)n * 8 + i];

    // u = relu(x@u1a + agg@u1b + ub1)
    float4 u[8];
#pragma unroll
    for (int i = 0; i < 8; i++) u[i] = s_ub1[i];
#pragma unroll
    for (int k = 0; k < 32; k++) {
        float f = COMP(xr[k >> 2], k & 3);
#pragma unroll
        for (int i = 0; i < 8; i++) u[i] = fma4(f, s_u1a[k * 8 + i], u[i]);
    }
#pragma unroll
    for (int k = 0; k < 32; k++) {
        float f = COMP(agg[k >> 2], k & 3);
#pragma unroll
        for (int i = 0; i < 8; i++) u[i] = fma4(f, s_u1b[k * 8 + i], u[i]);
    }
#pragma unroll
    for (int i = 0; i < 8; i++) u[i] = relu4(u[i]);

    // y = u @ uw2 + ub2   (new x)
    float4 y[8];
#pragma unroll
    for (int i = 0; i < 8; i++) y[i] = s_ub2[i];
#pragma unroll
    for (int k = 0; k < 32; k++) {
        float f = COMP(u[k >> 2], k & 3);
#pragma unroll
        for (int i = 0; i < 8; i++) y[i] = fma4(f, s_uw2[k * 8 + i], y[i]);
    }

    if (!last) {
        // A,B for next layer
        float4 a[8], b[8];
#pragma unroll
        for (int i = 0; i < 8; i++) { a[i] = make_float4(0,0,0,0); b[i] = make_float4(0,0,0,0); }
#pragma unroll
        for (int k = 0; k < 32; k++) {
            float f = COMP(y[k >> 2], k & 3);
#pragma unroll
            for (int i = 0; i < 8; i++) {
                a[i] = fma4(f, s_e1[k * 8 + i], a[i]);
                b[i] = fma4(f, s_e2[k * 8 + i], b[i]);
            }
        }
#pragma unroll
        for (int i = 0; i < 8; i++) {
            g_x[(size_t)n * 8 + i] = y[i];
            g_A[(size_t)n * 8 + i] = a[i];
            g_B[(size_t)n * 8 + i] = b[i];
        }
    } else {
        // out = y @ out_w + out_b
        float4 o[8];
#pragma unroll
        for (int i = 0; i < 8; i++) o[i] = s_eb[i];
#pragma unroll
        for (int k = 0; k < 32; k++) {
            float f = COMP(y[k >> 2], k & 3);
#pragma unroll
            for (int i = 0; i < 8; i++) o[i] = fma4(f, s_e1[k * 8 + i], o[i]);
        }
        float4* orow = (float4*)(outp + (size_t)n * 32);
#pragma unroll
        for (int i = 0; i < 8; i++) orow[i] = o[i];
    }
}

// ---------------- launch ----------------
extern "C" void kernel_launch(void* const* d_in, const int* in_sizes, int n_in,
                              void* d_out, int out_size) {
    const float* node_feat = (const float*)d_in[0];
    const float* pos       = (const float*)d_in[1];
    const void*  ei        = d_in[2];
    const float* enc_w1    = (const float*)d_in[3];
    const float* enc_b1    = (const float*)d_in[4];
    const float* enc_w2    = (const float*)d_in[5];
    const float* enc_b2    = (const float*)d_in[6];
    const float* msg_w1    = (const float*)d_in[7];   // [3, 65, 32]
    const float* msg_b1    = (const float*)d_in[8];
    const float* msg_w2    = (const float*)d_in[9];
    const float* msg_b2    = (const float*)d_in[10];
    const float* upd_w1    = (const float*)d_in[11];
    const float* upd_b1    = (const float*)d_in[12];
    const float* upd_w2    = (const float*)d_in[13];
    const float* upd_b2    = (const float*)d_in[14];
    const float* out_w     = (const float*)d_in[15];
    const float* out_b     = (const float*)d_in[16];
    float* out = (float*)d_out;

    const int NODE_BLOCKS = (N_NODES + 127) / 128;
    const int EDGE_BLOCKS = (N_EDGES + 255) / 256;
    const int AGG_BLOCKS  = (N_NODES * 32 + 127) / 128;

    detect_kernel<<<1, 32>>>((const int*)ei);
    zero_hist_kernel<<<(N_NODES + 255) / 256, 256>>>();
    decode_kernel<<<EDGE_BLOCKS, 256>>>(ei);
    scan1_kernel<<<N_SBLOCKS, 512>>>();
    scan2_kernel<<<1, 256>>>();
    scan3_kernel<<<N_SBLOCKS, 512>>>();
    scatter_kernel<<<EDGE_BLOCKS, 256>>>(pos);
    encoder_kernel<<<NODE_BLOCKS, 128>>>(node_feat, enc_w1, enc_b1, enc_w2, enc_b2,
                                         msg_w1 /* layer 0 */);

    for (int l = 0; l < 3; l++) {
        const float* w1 = msg_w1 + (size_t)l * 65 * 32;
        agg_kernel<<<AGG_BLOCKS, 128>>>(w1 + 64 * 32, msg_b1 + (size_t)l * 32);
        int last = (l == 2);
        const float* e1p = last ? out_w : msg_w1 + (size_t)(l + 1) * 65 * 32;
        const float* e2p = last ? out_w : msg_w1 + (size_t)(l + 1) * 65 * 32 + 1024;
        update_kernel<<<NODE_BLOCKS, 128>>>(
            msg_w2 + (size_t)l * 32 * 32, msg_b2 + (size_t)l * 32,
            upd_w1 + (size_t)l * 64 * 32, upd_b1 + (size_t)l * 32,
            upd_w2 + (size_t)l * 32 * 32, upd_b2 + (size_t)l * 32,
            e1p, e2p, out_b, out, last);
    }
}

// round 6
// speedup vs baseline: 2.3371x; 1.2143x over previous
#include <cuda_runtime.h>
#include <math.h>

#define N_NODES 100000
#define N_EDGES 1600000
#define HID 32
#define N_SBLOCKS ((N_NODES + 511) / 512)

// ---------------- device scratch ----------------
__device__ int    g_i64;
__device__ float4 g_h  [N_NODES * 8];       // hidden activation state [N,32]
__device__ float4 g_A  [N_NODES * 8];       // per-edge-MLP dst term
__device__ float4 g_B  [N_NODES * 8];       // per-edge-MLP src term
__device__ float4 g_agg[N_NODES * 8];
__device__ int    g_src [N_EDGES];
__device__ int    g_dst [N_EDGES];
__device__ int2   g_epack[N_EDGES];
__device__ int    g_hist[N_NODES];
__device__ int    g_off [N_NODES];
__device__ int    g_cur [N_NODES];
__device__ int    g_bsum[N_SBLOCKS];

// folded matrices/vectors (computed per launch by precompute_kernel)
__device__ float  c_Pa[3][1024], c_Pb[3][1024], c_P1[3][1024], c_P2[3][1024], c_Po[1024];
__device__ float  c_qa[3][32],  c_qb[3][32],  c_q1[3][32],  c_v[3][32],  c_qo[32];

// ---------------- helpers ----------------
__device__ __forceinline__ float4 fma4(float f, float4 w, float4 a) {
    a.x = fmaf(f, w.x, a.x); a.y = fmaf(f, w.y, a.y);
    a.z = fmaf(f, w.z, a.z); a.w = fmaf(f, w.w, a.w);
    return a;
}
__device__ __forceinline__ float4 add4(float4 a, float4 b) {
    a.x += b.x; a.y += b.y; a.z += b.z; a.w += b.w; return a;
}
__device__ __forceinline__ float4 relu4(float4 v) {
    v.x = fmaxf(v.x, 0.f); v.y = fmaxf(v.y, 0.f);
    v.z = fmaxf(v.z, 0.f); v.w = fmaxf(v.w, 0.f); return v;
}
#define COMP(v, c) ((c) == 0 ? (v).x : (c) == 1 ? (v).y : (c) == 2 ? (v).z : (v).w)

__device__ __forceinline__ ulonglong2 pack4(float4 v) {
    ulonglong2 r;
    asm("mov.b64 %0, {%1, %2};" : "=l"(r.x) : "f"(v.x), "f"(v.y));
    asm("mov.b64 %0, {%1, %2};" : "=l"(r.y) : "f"(v.z), "f"(v.w));
    return r;
}
__device__ __forceinline__ float4 unpack4(ulonglong2 v) {
    float4 r;
    asm("mov.b64 {%0, %1}, %2;" : "=f"(r.x), "=f"(r.y) : "l"(v.x));
    asm("mov.b64 {%0, %1}, %2;" : "=f"(r.z), "=f"(r.w) : "l"(v.y));
    return r;
}

// acc[8] += x(32, as float4 xr[8]) @ W(smem float4[32*8]), packed f32x2 math
__device__ __forceinline__ void gemv32(const float4* __restrict__ sW,
                                       const float4* xr, ulonglong2* acc) {
#pragma unroll
    for (int k = 0; k < 32; k++) {
        float f = COMP(xr[k >> 2], k & 3);
        unsigned long long f2;
        asm("mov.b64 %0, {%1, %1};" : "=l"(f2) : "f"(f));
        const ulonglong2* w = (const ulonglong2*)(sW + k * 8);
#pragma unroll
        for (int i = 0; i < 8; i++) {
            ulonglong2 wv = w[i];
            asm("fma.rn.f32x2 %0, %1, %2, %0;" : "+l"(acc[i].x) : "l"(f2), "l"(wv.x));
            asm("fma.rn.f32x2 %0, %1, %2, %0;" : "+l"(acc[i].y) : "l"(f2), "l"(wv.y));
        }
    }
}

// ---------------- edge-index dtype detection ----------------
__global__ void detect_kernel(const int* ei32) {
    if (blockIdx.x == 0 && threadIdx.x == 0) {
        int any = 0;
        for (int i = 1; i < 512; i += 2) any |= ei32[i];
        g_i64 = (any == 0) ? 1 : 0;
    }
}

__global__ void zero_hist_kernel() {
    int n = blockIdx.x * blockDim.x + threadIdx.x;
    if (n < N_NODES) g_hist[n] = 0;
}

__global__ void decode_kernel(const void* ei) {
    int e = blockIdx.x * blockDim.x + threadIdx.x;
    if (e >= N_EDGES) return;
    int src, dst;
    if (g_i64) {
        const long long* p = (const long long*)ei;
        src = (int)p[e]; dst = (int)p[N_EDGES + e];
    } else {
        const int* p = (const int*)ei;
        src = p[e]; dst = p[N_EDGES + e];
    }
    g_src[e] = src;
    g_dst[e] = dst;
    atomicAdd(&g_hist[dst], 1);
}

// ---------------- exclusive scan ----------------
__global__ void __launch_bounds__(512) scan1_kernel() {
    __shared__ int s[512];
    int tid = threadIdx.x;
    int i = blockIdx.x * 512 + tid;
    int v = (i < N_NODES) ? g_hist[i] : 0;
    s[tid] = v;
    __syncthreads();
#pragma unroll
    for (int off = 1; off < 512; off <<= 1) {
        int t = (tid >= off) ? s[tid - off] : 0;
        __syncthreads();
        s[tid] += t;
        __syncthreads();
    }
    if (i < N_NODES) g_off[i] = s[tid] - v;
    if (tid == 511) g_bsum[blockIdx.x] = s[511];
}

__global__ void __launch_bounds__(256) scan2_kernel() {
    __shared__ int s[256];
    int tid = threadIdx.x;
    int v = (tid < N_SBLOCKS) ? g_bsum[tid] : 0;
    s[tid] = v;
    __syncthreads();
#pragma unroll
    for (int off = 1; off < 256; off <<= 1) {
        int t = (tid >= off) ? s[tid - off] : 0;
        __syncthreads();
        s[tid] += t;
        __syncthreads();
    }
    if (tid < N_SBLOCKS) g_bsum[tid] = s[tid] - v;
}

__global__ void __launch_bounds__(512) scan3_kernel() {
    int i = blockIdx.x * 512 + threadIdx.x;
    if (i >= N_NODES) return;
    int off = g_off[i] + g_bsum[i >> 9];
    g_off[i] = off;
    g_cur[i] = off;
}

__global__ void scatter_kernel(const float* __restrict__ pos) {
    int e = blockIdx.x * blockDim.x + threadIdx.x;
    if (e >= N_EDGES) return;
    int src = g_src[e];
    int dst = g_dst[e];
    float dx = pos[dst * 3 + 0] - pos[src * 3 + 0];
    float dy = pos[dst * 3 + 1] - pos[src * 3 + 1];
    float dz = pos[dst * 3 + 2] - pos[src * 3 + 2];
    float dist = sqrtf(dx * dx + dy * dy + dz * dz);
    int p = atomicAdd(&g_cur[dst], 1);
    g_epack[p] = make_int2(src, __float_as_int(dist));
}

// ---------------- precompute folded matrices ----------------
// Pa[l] = Wp(l)   @ msg_w1[l][0:32]     qa[l] = cp(l)@msg_w1[l][0:32]
// Pb[l] = Wp(l)   @ msg_w1[l][32:64]    qb[l] = cp(l)@msg_w1[l][32:64]
// P1[l] = Wp(l)   @ upd_w1[l][0:32]     q1[l] = cp(l)@upd_w1[l][0:32] + upd_b1[l]
// P2[l] = msg_w2[l]@upd_w1[l][32:64]    v[l]  = msg_b2[l]@upd_w1[l][32:64]
// Po    = upd_w2[2]@out_w               qo    = upd_b2[2]@out_w + out_b
// Wp(0)=enc_w2, Wp(l)=upd_w2[l-1];  cp(0)=enc_b2, cp(l)=upd_b2[l-1]
__global__ void __launch_bounds__(256) precompute_kernel(
    const float* __restrict__ enc_w2, const float* __restrict__ enc_b2,
    const float* __restrict__ msg_w1, const float* __restrict__ msg_b1,
    const float* __restrict__ msg_w2, const float* __restrict__ msg_b2,
    const float* __restrict__ upd_w1, const float* __restrict__ upd_b1,
    const float* __restrict__ upd_w2, const float* __restrict__ upd_b2,
    const float* __restrict__ out_w, const float* __restrict__ out_b) {
    int b = blockIdx.x;
    int t = threadIdx.x;
    if (b < 13) {
        int l = (b < 12) ? (b % 3) : 2;
        int kind = (b < 12) ? (b / 3) : 4;
        const float* Wp = (l == 0) ? enc_w2 : upd_w2 + (size_t)(l - 1) * 1024;
        const float* L; const float* R; float* P;
        switch (kind) {
            case 0: L = Wp;                      R = msg_w1 + (size_t)l * 2080;        P = c_Pa[l]; break;
            case 1: L = Wp;                      R = msg_w1 + (size_t)l * 2080 + 1024; P = c_Pb[l]; break;
            case 2: L = Wp;                      R = upd_w1 + (size_t)l * 2048;        P = c_P1[l]; break;
            case 3: L = msg_w2 + (size_t)l*1024; R = upd_w1 + (size_t)l * 2048 + 1024; P = c_P2[l]; break;
            default: L = upd_w2 + 2048;          R = out_w;                            P = c_Po;    break;
        }
        for (int e = t; e < 1024; e += 256) {
            int i = e >> 5, j = e & 31;
            float s = 0.f;
            for (int k = 0; k < 32; k++) s = fmaf(L[i * 32 + k], R[k * 32 + j], s);
            P[e] = s;
        }
    } else {
        // vectors: 13 x 32
        for (int e = t; e < 416; e += 256) {
            int vid = e >> 5, j = e & 31;
            int l = vid % 3;
            const float* cp = (l == 0) ? enc_b2 : upd_b2 + (size_t)(l - 1) * 32;
            float s = 0.f;
            if (vid < 3) {          // qa
                const float* R = msg_w1 + (size_t)l * 2080;
                for (int k = 0; k < 32; k++) s = fmaf(cp[k], R[k * 32 + j], s);
                c_qa[l][j] = s;
            } else if (vid < 6) {   // qb
                const float* R = msg_w1 + (size_t)l * 2080 + 1024;
                for (int k = 0; k < 32; k++) s = fmaf(cp[k], R[k * 32 + j], s);
                c_qb[l][j] = s;
            } else if (vid < 9) {   // q1
                const float* R = upd_w1 + (size_t)l * 2048;
                for (int k = 0; k < 32; k++) s = fmaf(cp[k], R[k * 32 + j], s);
                c_q1[l][j] = s + upd_b1[l * 32 + j];
            } else if (vid < 12) {  // v
                const float* R = upd_w1 + (size_t)l * 2048 + 1024;
                const float* mb = msg_b2 + (size_t)l * 32;
                for (int k = 0; k < 32; k++) s = fmaf(mb[k], R[k * 32 + j], s);
                c_v[l][j] = s;
            } else {                // qo
                const float* ub = upd_b2 + 2 * 32;
                for (int k = 0; k < 32; k++) s = fmaf(ub[k], out_w[k * 32 + j], s);
                c_qo[j] = s + out_b[j];
            }
        }
    }
}

// ---------------- encoder: h = relu(feat@w1+b1); A=h@Pa0+qa0; B=h@Pb0+qb0 ----------------
__global__ void __launch_bounds__(128) encoder_kernel(
    const float* __restrict__ feat,
    const float* __restrict__ w1, const float* __restrict__ b1) {
    __shared__ float  s_feat[128 * 33];
    __shared__ float4 s_w1[64 * 8];
    __shared__ float4 s_pa[256], s_pb[256];
    __shared__ float4 s_b1[8], s_qa[8], s_qb[8];
    for (int i = threadIdx.x; i < 512; i += 128) s_w1[i] = ((const float4*)w1)[i];
    for (int i = threadIdx.x; i < 256; i += 128) {
        s_pa[i] = ((const float4*)c_Pa[0])[i];
        s_pb[i] = ((const float4*)c_Pb[0])[i];
    }
    if (threadIdx.x < 8) {
        s_b1[threadIdx.x] = ((const float4*)b1)[threadIdx.x];
        s_qa[threadIdx.x] = ((const float4*)c_qa[0])[threadIdx.x];
        s_qb[threadIdx.x] = ((const float4*)c_qb[0])[threadIdx.x];
    }
    __syncthreads();
    int base = blockIdx.x * 128;
    int n = base + threadIdx.x;
    bool act = (n < N_NODES);

    ulonglong2 hacc[8];
#pragma unroll
    for (int i = 0; i < 8; i++) hacc[i] = pack4(s_b1[i]);

#pragma unroll
    for (int half = 0; half < 2; half++) {
        for (int j = threadIdx.x; j < 128 * 32; j += 128) {
            int r = j >> 5, col = j & 31;
            int nn = base + r;
            s_feat[r * 33 + col] =
                (nn < N_NODES) ? feat[(size_t)nn * 64 + half * 32 + col] : 0.f;
        }
        __syncthreads();
        const float* frow = &s_feat[threadIdx.x * 33];
#pragma unroll 8
        for (int k = 0; k < 32; k++) {
            float f = frow[k];
            unsigned long long f2;
            asm("mov.b64 %0, {%1, %1};" : "=l"(f2) : "f"(f));
            const ulonglong2* w = (const ulonglong2*)(s_w1 + (half * 32 + k) * 8);
#pragma unroll
            for (int i = 0; i < 8; i++) {
                ulonglong2 wv = w[i];
                asm("fma.rn.f32x2 %0, %1, %2, %0;" : "+l"(hacc[i].x) : "l"(f2), "l"(wv.x));
                asm("fma.rn.f32x2 %0, %1, %2, %0;" : "+l"(hacc[i].y) : "l"(f2), "l"(wv.y));
            }
        }
        __syncthreads();
    }
    float4 h[8];
#pragma unroll
    for (int i = 0; i < 8; i++) h[i] = relu4(unpack4(hacc[i]));

    ulonglong2 a[8], b[8];
#pragma unroll
    for (int i = 0; i < 8; i++) { a[i] = pack4(s_qa[i]); b[i] = pack4(s_qb[i]); }
    gemv32(s_pa, h, a);
    gemv32(s_pb, h, b);

    if (act) {
        ulonglong2* ph = (ulonglong2*)&g_h[(size_t)n * 8];
        ulonglong2* pa = (ulonglong2*)&g_A[(size_t)n * 8];
        ulonglong2* pb = (ulonglong2*)&g_B[(size_t)n * 8];
#pragma unroll
        for (int i = 0; i < 8; i++) {
            ph[i] = pack4(h[i]);
            pa[i] = a[i];
            pb[i] = b[i];
        }
    }
}

// ---------------- per layer: agg[n] = sum_e relu(A[n] + B[src_e] + d_e*c + b1) ----------------
__global__ void __launch_bounds__(128) agg_kernel(
    const float* __restrict__ w1c, const float* __restrict__ b1) {
    int n = (blockIdx.x * 128 + threadIdx.x) >> 5;
    if (n >= N_NODES) return;
    int lane = threadIdx.x & 31;
    int c = lane & 7;
    int slot = lane >> 3;

    float4 cv = __ldg(((const float4*)w1c) + c);
    float4 bb = __ldg(((const float4*)b1) + c);

    int start = __ldg(&g_off[n]);
    int end = start + __ldg(&g_hist[n]);

    float4 ab = add4(g_A[(size_t)n * 8 + c], bb);
    float4 acc = make_float4(0.f, 0.f, 0.f, 0.f);

    int i = start + slot;
    bool valid = (i < end);
    int2 sd = valid ? __ldg(&g_epack[i]) : make_int2(0, 0);
    while (valid) {
        int nxt = i + 4;
        bool nv = (nxt < end);
        int2 sd2 = nv ? __ldg(&g_epack[nxt]) : make_int2(0, 0);
        int src = sd.x;
        float d = __int_as_float(sd.y);
        float4 b = g_B[(size_t)src * 8 + c];
        acc = add4(acc, relu4(fma4(d, cv, add4(ab, b))));
        i = nxt; sd = sd2; valid = nv;
    }
#pragma unroll
    for (int m = 8; m <= 16; m <<= 1) {
        acc.x += __shfl_xor_sync(0xffffffffu, acc.x, m);
        acc.y += __shfl_xor_sync(0xffffffffu, acc.y, m);
        acc.z += __shfl_xor_sync(0xffffffffu, acc.z, m);
        acc.w += __shfl_xor_sync(0xffffffffu, acc.w, m);
    }
    if (lane < 8) g_agg[(size_t)n * 8 + lane] = acc;
}

// ---------------- per layer update (folded):
// u = relu(h@P1 + aggH@P2 + deg*v + q1); then {A,B}next = u@{Pa,Pb}+{qa,qb} or out = u@Po+qo
__global__ void __launch_bounds__(128) update_kernel(int l, int last, float* __restrict__ outp) {
    __shared__ float4 s_p1[256], s_p2[256], s_pc[256], s_pd[256];
    __shared__ float4 s_q1[8], s_v[8], s_qc[8], s_qd[8];
    {
        const float* P1 = c_P1[l];
        const float* P2 = c_P2[l];
        const float* Pc = last ? c_Po : c_Pa[l + 1 < 3 ? l + 1 : 0];
        const float* Pd = last ? c_Po : c_Pb[l + 1 < 3 ? l + 1 : 0];
        for (int i = threadIdx.x; i < 256; i += 128) {
            s_p1[i] = ((const float4*)P1)[i];
            s_p2[i] = ((const float4*)P2)[i];
            s_pc[i] = ((const float4*)Pc)[i];
            s_pd[i] = ((const float4*)Pd)[i];
        }
        if (threadIdx.x < 8) {
            s_q1[threadIdx.x] = ((const float4*)c_q1[l])[threadIdx.x];
            s_v[threadIdx.x]  = ((const float4*)c_v[l])[threadIdx.x];
            const float* qc = last ? c_qo : c_qa[l + 1 < 3 ? l + 1 : 0];
            const float* qd = last ? c_qo : c_qb[l + 1 < 3 ? l + 1 : 0];
            s_qc[threadIdx.x] = ((const float4*)qc)[threadIdx.x];
            s_qd[threadIdx.x] = ((const float4*)qd)[threadIdx.x];
        }
    }
    __syncthreads();
    int n = blockIdx.x * blockDim.x + threadIdx.x;
    if (n >= N_NODES) return;

    float deg = (float)g_hist[n];
    ulonglong2 uacc[8];
#pragma unroll
    for (int i = 0; i < 8; i++) {
        float4 q = s_q1[i], vv = s_v[i];
        uacc[i] = pack4(make_float4(fmaf(deg, vv.x, q.x), fmaf(deg, vv.y, q.y),
                                    fmaf(deg, vv.z, q.z), fmaf(deg, vv.w, q.w)));
    }
    float4 hr[8];
#pragma unroll
    for (int i = 0; i < 8; i++) hr[i] = g_h[(size_t)n * 8 + i];
    gemv32(s_p1, hr, uacc);
    float4 ar[8];
#pragma unroll
    for (int i = 0; i < 8; i++) ar[i] = g_agg[(size_t)n * 8 + i];
    gemv32(s_p2, ar, uacc);

    float4 u[8];
#pragma unroll
    for (int i = 0; i < 8; i++) u[i] = relu4(unpack4(uacc[i]));

    ulonglong2 cacc[8];
#pragma unroll
    for (int i = 0; i < 8; i++) cacc[i] = pack4(s_qc[i]);
    gemv32(s_pc, u, cacc);

    if (!last) {
        ulonglong2 dacc[8];
#pragma unroll
        for (int i = 0; i < 8; i++) dacc[i] = pack4(s_qd[i]);
        gemv32(s_pd, u, dacc);
        ulonglong2* ph = (ulonglong2*)&g_h[(size_t)n * 8];
        ulonglong2* pa = (ulonglong2*)&g_A[(size_t)n * 8];
        ulonglong2* pb = (ulonglong2*)&g_B[(size_t)n * 8];
#pragma unroll
        for (int i = 0; i < 8; i++) {
            ph[i] = pack4(u[i]);
            pa[i] = cacc[i];
            pb[i] = dacc[i];
        }
    } else {
        ulonglong2* orow = (ulonglong2*)(outp + (size_t)n * 32);
#pragma unroll
        for (int i = 0; i < 8; i++) orow[i] = cacc[i];
    }
}

// ---------------- launch ----------------
extern "C" void kernel_launch(void* const* d_in, const int* in_sizes, int n_in,
                              void* d_out, int out_size) {
    const float* node_feat = (const float*)d_in[0];
    const float* pos       = (const float*)d_in[1];
    const void*  ei        = d_in[2];
    const float* enc_w1    = (const float*)d_in[3];
    const float* enc_b1    = (const float*)d_in[4];
    const float* enc_w2    = (const float*)d_in[5];
    const float* enc_b2    = (const float*)d_in[6];
    const float* msg_w1    = (const float*)d_in[7];
    const float* msg_b1    = (const float*)d_in[8];
    const float* msg_w2    = (const float*)d_in[9];
    const float* msg_b2    = (const float*)d_in[10];
    const float* upd_w1    = (const float*)d_in[11];
    const float* upd_b1    = (const float*)d_in[12];
    const float* upd_w2    = (const float*)d_in[13];
    const float* upd_b2    = (const float*)d_in[14];
    const float* out_w     = (const float*)d_in[15];
    const float* out_b     = (const float*)d_in[16];
    float* out = (float*)d_out;

    const int NODE_BLOCKS = (N_NODES + 127) / 128;
    const int EDGE_BLOCKS = (N_EDGES + 255) / 256;
    const int AGG_BLOCKS  = (N_NODES * 32 + 127) / 128;

    detect_kernel<<<1, 32>>>((const int*)ei);
    zero_hist_kernel<<<(N_NODES + 255) / 256, 256>>>();
    decode_kernel<<<EDGE_BLOCKS, 256>>>(ei);
    scan1_kernel<<<N_SBLOCKS, 512>>>();
    scan2_kernel<<<1, 256>>>();
    scan3_kernel<<<N_SBLOCKS, 512>>>();
    scatter_kernel<<<EDGE_BLOCKS, 256>>>(pos);
    precompute_kernel<<<14, 256>>>(enc_w2, enc_b2, msg_w1, msg_b1, msg_w2, msg_b2,
                                   upd_w1, upd_b1, upd_w2, upd_b2, out_w, out_b);
    encoder_kernel<<<NODE_BLOCKS, 128>>>(node_feat, enc_w1, enc_b1);

    for (int l = 0; l < 3; l++) {
        const float* w1 = msg_w1 + (size_t)l * 65 * 32;
        agg_kernel<<<AGG_BLOCKS, 128>>>(w1 + 64 * 32, msg_b1 + (size_t)l * 32);
        update_kernel<<<NODE_BLOCKS, 128>>>(l, l == 2, out);
    }
}

// round 7
// speedup vs baseline: 2.3407x; 1.0015x over previous
#include <cuda_runtime.h>
#include <math.h>

#define N_NODES 100000
#define N_EDGES 1600000
#define HID 32

#define SCAN_T 512
#define SCAN_ITEMS 8
#define SCAN_PART (SCAN_T * SCAN_ITEMS)                 // 4096
#define N_PARTS ((N_NODES + SCAN_PART - 1) / SCAN_PART) // 25

// ---------------- device scratch ----------------
__device__ float4 g_h  [N_NODES * 8];
__device__ float4 g_A  [N_NODES * 8];
__device__ float4 g_B  [N_NODES * 8];
__device__ float4 g_agg[N_NODES * 8];
__device__ float4 g_pos4[N_NODES];
__device__ int    g_src [N_EDGES];
__device__ int    g_dst [N_EDGES];
__device__ int2   g_epack[N_EDGES];
__device__ int    g_hist[N_NODES];
__device__ int    g_off [N_NODES];
__device__ int    g_cur [N_NODES];
__device__ unsigned long long g_state[N_PARTS];

// folded matrices/vectors
__device__ float  c_Pa[3][1024], c_Pb[3][1024], c_P1[3][1024], c_P2[3][1024], c_Po[1024];
__device__ float  c_qa[3][32],  c_qb[3][32],  c_q1[3][32],  c_v[3][32],  c_qo[32];

// ---------------- helpers ----------------
__device__ __forceinline__ float4 fma4(float f, float4 w, float4 a) {
    a.x = fmaf(f, w.x, a.x); a.y = fmaf(f, w.y, a.y);
    a.z = fmaf(f, w.z, a.z); a.w = fmaf(f, w.w, a.w);
    return a;
}
__device__ __forceinline__ float4 add4(float4 a, float4 b) {
    a.x += b.x; a.y += b.y; a.z += b.z; a.w += b.w; return a;
}
__device__ __forceinline__ float4 relu4(float4 v) {
    v.x = fmaxf(v.x, 0.f); v.y = fmaxf(v.y, 0.f);
    v.z = fmaxf(v.z, 0.f); v.w = fmaxf(v.w, 0.f); return v;
}
#define COMP(v, c) ((c) == 0 ? (v).x : (c) == 1 ? (v).y : (c) == 2 ? (v).z : (v).w)

__device__ __forceinline__ ulonglong2 pack4(float4 v) {
    ulonglong2 r;
    asm("mov.b64 %0, {%1, %2};" : "=l"(r.x) : "f"(v.x), "f"(v.y));
    asm("mov.b64 %0, {%1, %2};" : "=l"(r.y) : "f"(v.z), "f"(v.w));
    return r;
}
__device__ __forceinline__ float4 unpack4(ulonglong2 v) {
    float4 r;
    asm("mov.b64 {%0, %1}, %2;" : "=f"(r.x), "=f"(r.y) : "l"(v.x));
    asm("mov.b64 {%0, %1}, %2;" : "=f"(r.z), "=f"(r.w) : "l"(v.y));
    return r;
}

__device__ __forceinline__ void gemv32(const float4* __restrict__ sW,
                                       const float4* xr, ulonglong2* acc) {
#pragma unroll
    for (int k = 0; k < 32; k++) {
        float f = COMP(xr[k >> 2], k & 3);
        unsigned long long f2;
        asm("mov.b64 %0, {%1, %1};" : "=l"(f2) : "f"(f));
        const ulonglong2* w = (const ulonglong2*)(sW + k * 8);
#pragma unroll
        for (int i = 0; i < 8; i++) {
            ulonglong2 wv = w[i];
            asm("fma.rn.f32x2 %0, %1, %2, %0;" : "+l"(acc[i].x) : "l"(f2), "l"(wv.x));
            asm("fma.rn.f32x2 %0, %1, %2, %0;" : "+l"(acc[i].y) : "l"(f2), "l"(wv.y));
        }
    }
}

// ---------------- decode (fused dtype detect) + histogram ----------------
__global__ void decode_kernel(const void* ei) {
    __shared__ int s_i64;
    if (threadIdx.x < 32) {
        // int64 edge values < 1e5 -> odd 32-bit words all zero; int32 layout -> random nonzero
        int v = ((const int*)ei)[2 * threadIdx.x + 1];
        unsigned m = __ballot_sync(0xffffffffu, v != 0);
        if (threadIdx.x == 0) s_i64 = (m == 0);
    }
    __syncthreads();
    int e = blockIdx.x * blockDim.x + threadIdx.x;
    if (e >= N_EDGES) return;
    int src, dst;
    if (s_i64) {
        const long long* p = (const long long*)ei;
        src = (int)p[e]; dst = (int)p[N_EDGES + e];
    } else {
        const int* p = (const int*)ei;
        src = p[e]; dst = p[N_EDGES + e];
    }
    g_src[e] = src;
    g_dst[e] = dst;
    atomicAdd(&g_hist[dst], 1);
}

// ---------------- pack pos into float4 ----------------
__global__ void pospack_kernel(const float* __restrict__ pos) {
    int n = blockIdx.x * blockDim.x + threadIdx.x;
    if (n >= N_NODES) return;
    g_pos4[n] = make_float4(pos[n * 3 + 0], pos[n * 3 + 1], pos[n * 3 + 2], 0.f);
}

// ---------------- single-pass decoupled-lookback exclusive scan ----------------
__global__ void __launch_bounds__(SCAN_T) scan_kernel() {
    __shared__ int s[SCAN_T];
    __shared__ int s_prefix;
    int part = blockIdx.x;
    int tid = threadIdx.x;
    int base = part * SCAN_PART + tid * SCAN_ITEMS;
    int v[SCAN_ITEMS];
    int tsum = 0;
#pragma unroll
    for (int j = 0; j < SCAN_ITEMS; j++) {
        int idx = base + j;
        v[j] = (idx < N_NODES) ? g_hist[idx] : 0;
        tsum += v[j];
    }
    s[tid] = tsum;
    __syncthreads();
#pragma unroll
    for (int off = 1; off < SCAN_T; off <<= 1) {
        int t = (tid >= off) ? s[tid - off] : 0;
        __syncthreads();
        s[tid] += t;
        __syncthreads();
    }
    int texcl = s[tid] - tsum;
    int btotal = s[SCAN_T - 1];

    if (tid == 0) {
        if (part == 0) {
            s_prefix = 0;
            atomicExch(&g_state[0], (2ULL << 32) | (unsigned)btotal);
        } else {
            atomicExch(&g_state[part], (1ULL << 32) | (unsigned)btotal);
            int pref = 0;
            int p = part - 1;
            while (true) {
                unsigned long long st;
                do { st = atomicAdd(&g_state[p], 0ULL); } while ((st >> 32) == 0);
                pref += (int)(unsigned)st;
                if ((st >> 32) == 2) break;
                p--;
            }
            s_prefix = pref;
            atomicExch(&g_state[part], (2ULL << 32) | (unsigned)(pref + btotal));
        }
    }
    __syncthreads();
    int excl = s_prefix + texcl;
#pragma unroll
    for (int j = 0; j < SCAN_ITEMS; j++) {
        int idx = base + j;
        if (idx < N_NODES) { g_off[idx] = excl; g_cur[idx] = excl; }
        excl += v[j];
    }
}

// ---------------- scatter edges into CSR order (by dst) ----------------
__global__ void scatter_kernel() {
    int e = blockIdx.x * blockDim.x + threadIdx.x;
    if (e >= N_EDGES) return;
    int src = g_src[e];
    int dst = g_dst[e];
    float4 pd = __ldg(&g_pos4[dst]);
    float4 ps = __ldg(&g_pos4[src]);
    float dx = pd.x - ps.x, dy = pd.y - ps.y, dz = pd.z - ps.z;
    float dist = sqrtf(dx * dx + dy * dy + dz * dz);
    int p = atomicAdd(&g_cur[dst], 1);
    g_epack[p] = make_int2(src, __float_as_int(dist));
}

// ---------------- precompute folded matrices ----------------
__global__ void __launch_bounds__(256) precompute_kernel(
    const float* __restrict__ enc_w2, const float* __restrict__ enc_b2,
    const float* __restrict__ msg_w1, const float* __restrict__ msg_b1,
    const float* __restrict__ msg_w2, const float* __restrict__ msg_b2,
    const float* __restrict__ upd_w1, const float* __restrict__ upd_b1,
    const float* __restrict__ upd_w2, const float* __restrict__ upd_b2,
    const float* __restrict__ out_w, const float* __restrict__ out_b) {
    int b = blockIdx.x;
    int t = threadIdx.x;
    if (b < 13) {
        int l = (b < 12) ? (b % 3) : 2;
        int kind = (b < 12) ? (b / 3) : 4;
        const float* Wp = (l == 0) ? enc_w2 : upd_w2 + (size_t)(l - 1) * 1024;
        const float* L; const float* R; float* P;
        switch (kind) {
            case 0: L = Wp;                      R = msg_w1 + (size_t)l * 2080;        P = c_Pa[l]; break;
            case 1: L = Wp;                      R = msg_w1 + (size_t)l * 2080 + 1024; P = c_Pb[l]; break;
            case 2: L = Wp;                      R = upd_w1 + (size_t)l * 2048;        P = c_P1[l]; break;
            case 3: L = msg_w2 + (size_t)l*1024; R = upd_w1 + (size_t)l * 2048 + 1024; P = c_P2[l]; break;
            default: L = upd_w2 + 2048;          R = out_w;                            P = c_Po;    break;
        }
        for (int e = t; e < 1024; e += 256) {
            int i = e >> 5, j = e & 31;
            float s = 0.f;
            for (int k = 0; k < 32; k++) s = fmaf(L[i * 32 + k], R[k * 32 + j], s);
            P[e] = s;
        }
    } else {
        for (int e = t; e < 416; e += 256) {
            int vid = e >> 5, j = e & 31;
            int l = vid % 3;
            const float* cp = (l == 0) ? enc_b2 : upd_b2 + (size_t)(l - 1) * 32;
            float s = 0.f;
            if (vid < 3) {
                const float* R = msg_w1 + (size_t)l * 2080;
                for (int k = 0; k < 32; k++) s = fmaf(cp[k], R[k * 32 + j], s);
                c_qa[l][j] = s;
            } else if (vid < 6) {
                const float* R = msg_w1 + (size_t)l * 2080 + 1024;
                for (int k = 0; k < 32; k++) s = fmaf(cp[k], R[k * 32 + j], s);
                c_qb[l][j] = s;
            } else if (vid < 9) {
                const float* R = upd_w1 + (size_t)l * 2048;
                for (int k = 0; k < 32; k++) s = fmaf(cp[k], R[k * 32 + j], s);
                c_q1[l][j] = s + upd_b1[l * 32 + j];
            } else if (vid < 12) {
                const float* R = upd_w1 + (size_t)l * 2048 + 1024;
                const float* mb = msg_b2 + (size_t)l * 32;
                for (int k = 0; k < 32; k++) s = fmaf(mb[k], R[k * 32 + j], s);
                c_v[l][j] = s;
            } else {
                const float* ub = upd_b2 + 2 * 32;
                for (int k = 0; k < 32; k++) s = fmaf(ub[k], out_w[k * 32 + j], s);
                c_qo[j] = s + out_b[j];
            }
        }
    }
}

// ---------------- encoder: h = relu(feat@w1+b1); A=h@Pa0+qa0; B=h@Pb0+qb0 ----------------
__global__ void __launch_bounds__(128) encoder_kernel(
    const float* __restrict__ feat,
    const float* __restrict__ w1, const float* __restrict__ b1) {
    __shared__ float  s_feat[128 * 33];
    __shared__ float4 s_w1[64 * 8];
    __shared__ float4 s_pa[256], s_pb[256];
    __shared__ float4 s_b1[8], s_qa[8], s_qb[8];
    for (int i = threadIdx.x; i < 512; i += 128) s_w1[i] = ((const float4*)w1)[i];
    for (int i = threadIdx.x; i < 256; i += 128) {
        s_pa[i] = ((const float4*)c_Pa[0])[i];
        s_pb[i] = ((const float4*)c_Pb[0])[i];
    }
    if (threadIdx.x < 8) {
        s_b1[threadIdx.x] = ((const float4*)b1)[threadIdx.x];
        s_qa[threadIdx.x] = ((const float4*)c_qa[0])[threadIdx.x];
        s_qb[threadIdx.x] = ((const float4*)c_qb[0])[threadIdx.x];
    }
    __syncthreads();
    int base = blockIdx.x * 128;
    int n = base + threadIdx.x;
    bool act = (n < N_NODES);

    ulonglong2 hacc[8];
#pragma unroll
    for (int i = 0; i < 8; i++) hacc[i] = pack4(s_b1[i]);

#pragma unroll
    for (int half = 0; half < 2; half++) {
        for (int j = threadIdx.x; j < 128 * 32; j += 128) {
            int r = j >> 5, col = j & 31;
            int nn = base + r;
            s_feat[r * 33 + col] =
                (nn < N_NODES) ? feat[(size_t)nn * 64 + half * 32 + col] : 0.f;
        }
        __syncthreads();
        const float* frow = &s_feat[threadIdx.x * 33];
#pragma unroll 8
        for (int k = 0; k < 32; k++) {
            float f = frow[k];
            unsigned long long f2;
            asm("mov.b64 %0, {%1, %1};" : "=l"(f2) : "f"(f));
            const ulonglong2* w = (const ulonglong2*)(s_w1 + (half * 32 + k) * 8);
#pragma unroll
            for (int i = 0; i < 8; i++) {
                ulonglong2 wv = w[i];
                asm("fma.rn.f32x2 %0, %1, %2, %0;" : "+l"(hacc[i].x) : "l"(f2), "l"(wv.x));
                asm("fma.rn.f32x2 %0, %1, %2, %0;" : "+l"(hacc[i].y) : "l"(f2), "l"(wv.y));
            }
        }
        __syncthreads();
    }
    float4 h[8];
#pragma unroll
    for (int i = 0; i < 8; i++) h[i] = relu4(unpack4(hacc[i]));

    ulonglong2 a[8], b[8];
#pragma unroll
    for (int i = 0; i < 8; i++) { a[i] = pack4(s_qa[i]); b[i] = pack4(s_qb[i]); }
    gemv32(s_pa, h, a);
    gemv32(s_pb, h, b);

    if (act) {
        ulonglong2* ph = (ulonglong2*)&g_h[(size_t)n * 8];
        ulonglong2* pa = (ulonglong2*)&g_A[(size_t)n * 8];
        ulonglong2* pb = (ulonglong2*)&g_B[(size_t)n * 8];
#pragma unroll
        for (int i = 0; i < 8; i++) {
            ph[i] = pack4(h[i]);
            pa[i] = a[i];
            pb[i] = b[i];
        }
    }
}

// ---------------- per layer: agg[n] = sum_e relu(A[n] + B[src_e] + d_e*c + b1) ----------------
// warp per node; lane c=lane&7 owns float4 component; slot=lane>>3 strides edges by 4.
// 2x unrolled: two independent gather chains in flight (MLP=2).
__global__ void __launch_bounds__(128) agg_kernel(
    const float* __restrict__ w1c, const float* __restrict__ b1) {
    int n = (blockIdx.x * 128 + threadIdx.x) >> 5;
    if (n >= N_NODES) return;
    int lane = threadIdx.x & 31;
    int c = lane & 7;
    int slot = lane >> 3;

    float4 cv = __ldg(((const float4*)w1c) + c);
    float4 bb = __ldg(((const float4*)b1) + c);

    int start = __ldg(&g_off[n]);
    int end = start + __ldg(&g_hist[n]);

    float4 ab = add4(g_A[(size_t)n * 8 + c], bb);
    float4 acc0 = make_float4(0.f, 0.f, 0.f, 0.f);
    float4 acc1 = make_float4(0.f, 0.f, 0.f, 0.f);

    int i = start + slot;
    for (; i + 4 < end; i += 8) {
        int2 sd0 = __ldg(&g_epack[i]);
        int2 sd1 = __ldg(&g_epack[i + 4]);
        float4 b0 = g_B[(size_t)sd0.x * 8 + c];
        float4 b1v = g_B[(size_t)sd1.x * 8 + c];
        acc0 = add4(acc0, relu4(fma4(__int_as_float(sd0.y), cv, add4(ab, b0))));
        acc1 = add4(acc1, relu4(fma4(__int_as_float(sd1.y), cv, add4(ab, b1v))));
    }
    if (i < end) {
        int2 sd = __ldg(&g_epack[i]);
        float4 b = g_B[(size_t)sd.x * 8 + c];
        acc0 = add4(acc0, relu4(fma4(__int_as_float(sd.y), cv, add4(ab, b))));
    }
    float4 acc = add4(acc0, acc1);
#pragma unroll
    for (int m = 8; m <= 16; m <<= 1) {
        acc.x += __shfl_xor_sync(0xffffffffu, acc.x, m);
        acc.y += __shfl_xor_sync(0xffffffffu, acc.y, m);
        acc.z += __shfl_xor_sync(0xffffffffu, acc.z, m);
        acc.w += __shfl_xor_sync(0xffffffffu, acc.w, m);
    }
    if (lane < 8) g_agg[(size_t)n * 8 + lane] = acc;
}

// ---------------- per layer update (folded) ----------------
__global__ void __launch_bounds__(128) update_kernel(int l, int last, float* __restrict__ outp) {
    __shared__ float4 s_p1[256], s_p2[256], s_pc[256], s_pd[256];
    __shared__ float4 s_q1[8], s_v[8], s_qc[8], s_qd[8];
    {
        const float* P1 = c_P1[l];
        const float* P2 = c_P2[l];
        const float* Pc = last ? c_Po : c_Pa[l + 1 < 3 ? l + 1 : 0];
        const float* Pd = last ? c_Po : c_Pb[l + 1 < 3 ? l + 1 : 0];
        for (int i = threadIdx.x; i < 256; i += 128) {
            s_p1[i] = ((const float4*)P1)[i];
            s_p2[i] = ((const float4*)P2)[i];
            s_pc[i] = ((const float4*)Pc)[i];
            s_pd[i] = ((const float4*)Pd)[i];
        }
        if (threadIdx.x < 8) {
            s_q1[threadIdx.x] = ((const float4*)c_q1[l])[threadIdx.x];
            s_v[threadIdx.x]  = ((const float4*)c_v[l])[threadIdx.x];
            const float* qc = last ? c_qo : c_qa[l + 1 < 3 ? l + 1 : 0];
            const float* qd = last ? c_qo : c_qb[l + 1 < 3 ? l + 1 : 0];
            s_qc[threadIdx.x] = ((const float4*)qc)[threadIdx.x];
            s_qd[threadIdx.x] = ((const float4*)qd)[threadIdx.x];
        }
    }
    __syncthreads();
    int n = blockIdx.x * blockDim.x + threadIdx.x;
    if (n >= N_NODES) return;

    float deg = (float)g_hist[n];
    ulonglong2 uacc[8];
#pragma unroll
    for (int i = 0; i < 8; i++) {
        float4 q = s_q1[i], vv = s_v[i];
        uacc[i] = pack4(make_float4(fmaf(deg, vv.x, q.x), fmaf(deg, vv.y, q.y),
                                    fmaf(deg, vv.z, q.z), fmaf(deg, vv.w, q.w)));
    }
    float4 hr[8];
#pragma unroll
    for (int i = 0; i < 8; i++) hr[i] = g_h[(size_t)n * 8 + i];
    gemv32(s_p1, hr, uacc);
    float4 ar[8];
#pragma unroll
    for (int i = 0; i < 8; i++) ar[i] = g_agg[(size_t)n * 8 + i];
    gemv32(s_p2, ar, uacc);

    float4 u[8];
#pragma unroll
    for (int i = 0; i < 8; i++) u[i] = relu4(unpack4(uacc[i]));

    ulonglong2 cacc[8];
#pragma unroll
    for (int i = 0; i < 8; i++) cacc[i] = pack4(s_qc[i]);
    gemv32(s_pc, u, cacc);

    if (!last) {
        ulonglong2 dacc[8];
#pragma unroll
        for (int i = 0; i < 8; i++) dacc[i] = pack4(s_qd[i]);
        gemv32(s_pd, u, dacc);
        ulonglong2* ph = (ulonglong2*)&g_h[(size_t)n * 8];
        ulonglong2* pa = (ulonglong2*)&g_A[(size_t)n * 8];
        ulonglong2* pb = (ulonglong2*)&g_B[(size_t)n * 8];
#pragma unroll
        for (int i = 0; i < 8; i++) {
            ph[i] = pack4(u[i]);
            pa[i] = cacc[i];
            pb[i] = dacc[i];
        }
    } else {
        ulonglong2* orow = (ulonglong2*)(outp + (size_t)n * 32);
#pragma unroll
        for (int i = 0; i < 8; i++) orow[i] = cacc[i];
    }
}

// ---------------- launch ----------------
extern "C" void kernel_launch(void* const* d_in, const int* in_sizes, int n_in,
                              void* d_out, int out_size) {
    const float* node_feat = (const float*)d_in[0];
    const float* pos       = (const float*)d_in[1];
    const void*  ei        = d_in[2];
    const float* enc_w1    = (const float*)d_in[3];
    const float* enc_b1    = (const float*)d_in[4];
    const float* enc_w2    = (const float*)d_in[5];
    const float* enc_b2    = (const float*)d_in[6];
    const float* msg_w1    = (const float*)d_in[7];
    const float* msg_b1    = (const float*)d_in[8];
    const float* msg_w2    = (const float*)d_in[9];
    const float* msg_b2    = (const float*)d_in[10];
    const float* upd_w1    = (const float*)d_in[11];
    const float* upd_b1    = (const float*)d_in[12];
    const float* upd_w2    = (const float*)d_in[13];
    const float* upd_b2    = (const float*)d_in[14];
    const float* out_w     = (const float*)d_in[15];
    const float* out_b     = (const float*)d_in[16];
    float* out = (float*)d_out;

    const int NODE_BLOCKS = (N_NODES + 127) / 128;
    const int EDGE_BLOCKS = (N_EDGES + 255) / 256;
    const int AGG_BLOCKS  = (N_NODES * 32 + 127) / 128;

    // zero hist + scan state via graph memset nodes (no kernel launch)
    void* p_hist = nullptr; void* p_state = nullptr;
    cudaGetSymbolAddress(&p_hist, g_hist);
    cudaGetSymbolAddress(&p_state, g_state);
    cudaMemsetAsync(p_hist, 0, N_NODES * sizeof(int), 0);
    cudaMemsetAsync(p_state, 0, N_PARTS * sizeof(unsigned long long), 0);

    decode_kernel<<<EDGE_BLOCKS, 256>>>(ei);
    pospack_kernel<<<(N_NODES + 255) / 256, 256>>>(pos);
    scan_kernel<<<N_PARTS, SCAN_T>>>();
    scatter_kernel<<<EDGE_BLOCKS, 256>>>();
    precompute_kernel<<<14, 256>>>(enc_w2, enc_b2, msg_w1, msg_b1, msg_w2, msg_b2,
                                   upd_w1, upd_b1, upd_w2, upd_b2, out_w, out_b);
    encoder_kernel<<<NODE_BLOCKS, 128>>>(node_feat, enc_w1, enc_b1);

    for (int l = 0; l < 3; l++) {
        const float* w1 = msg_w1 + (size_t)l * 65 * 32;
        agg_kernel<<<AGG_BLOCKS, 128>>>(w1 + 64 * 32, msg_b1 + (size_t)l * 32);
        update_kernel<<<NODE_BLOCKS, 128>>>(l, l == 2, out);
    }
}

// round 8
// speedup vs baseline: 2.4457x; 1.0448x over previous
#include <cuda_runtime.h>
#include <cuda_fp16.h>
#include <math.h>

#define N_NODES 100000
#define N_EDGES 1600000
#define HID 32

#define SCAN_T 512
#define SCAN_ITEMS 8
#define SCAN_PART (SCAN_T * SCAN_ITEMS)                 // 4096
#define N_PARTS ((N_NODES + SCAN_PART - 1) / SCAN_PART) // 25

// ---------------- device scratch ----------------
__device__ float4 g_h  [N_NODES * 8];
__device__ float4 g_A  [N_NODES * 8];
__device__ unsigned long long g_Bh[N_NODES * 8];   // fp16 B table: 8B per (node, comp)
__device__ float4 g_agg[N_NODES * 8];
__device__ float4 g_pos4[N_NODES];
__device__ int2   g_epack[N_EDGES];
// combined zero region: [0, N_NODES) = hist; [N_NODES, +2*N_PARTS) = scan state
__device__ __align__(8) int g_zero[N_NODES + 2 * N_PARTS];
__device__ int    g_off [N_NODES];
__device__ int    g_cur [N_NODES];

// folded matrices/vectors
__device__ float  c_Pa[3][1024], c_Pb[3][1024], c_P1[3][1024], c_P2[3][1024], c_Po[1024];
__device__ float  c_qa[3][32],  c_qb[3][32],  c_q1[3][32],  c_v[3][32],  c_qo[32];

// ---------------- helpers ----------------
__device__ __forceinline__ float4 fma4(float f, float4 w, float4 a) {
    a.x = fmaf(f, w.x, a.x); a.y = fmaf(f, w.y, a.y);
    a.z = fmaf(f, w.z, a.z); a.w = fmaf(f, w.w, a.w);
    return a;
}
__device__ __forceinline__ float4 add4(float4 a, float4 b) {
    a.x += b.x; a.y += b.y; a.z += b.z; a.w += b.w; return a;
}
__device__ __forceinline__ float4 relu4(float4 v) {
    v.x = fmaxf(v.x, 0.f); v.y = fmaxf(v.y, 0.f);
    v.z = fmaxf(v.z, 0.f); v.w = fmaxf(v.w, 0.f); return v;
}
#define COMP(v, c) ((c) == 0 ? (v).x : (c) == 1 ? (v).y : (c) == 2 ? (v).z : (v).w)

__device__ __forceinline__ ulonglong2 pack4(float4 v) {
    ulonglong2 r;
    asm("mov.b64 %0, {%1, %2};" : "=l"(r.x) : "f"(v.x), "f"(v.y));
    asm("mov.b64 %0, {%1, %2};" : "=l"(r.y) : "f"(v.z), "f"(v.w));
    return r;
}
__device__ __forceinline__ float4 unpack4(ulonglong2 v) {
    float4 r;
    asm("mov.b64 {%0, %1}, %2;" : "=f"(r.x), "=f"(r.y) : "l"(v.x));
    asm("mov.b64 {%0, %1}, %2;" : "=f"(r.z), "=f"(r.w) : "l"(v.y));
    return r;
}
__device__ __forceinline__ unsigned long long f4_to_h4(float4 v) {
    __half2 h0 = __floats2half2_rn(v.x, v.y);
    __half2 h1 = __floats2half2_rn(v.z, v.w);
    unsigned lo = *reinterpret_cast<unsigned*>(&h0);
    unsigned hi = *reinterpret_cast<unsigned*>(&h1);
    return (unsigned long long)lo | ((unsigned long long)hi << 32);
}
__device__ __forceinline__ float4 h4_to_f4(unsigned long long v) {
    unsigned lo = (unsigned)v, hi = (unsigned)(v >> 32);
    __half2 h0 = *reinterpret_cast<__half2*>(&lo);
    __half2 h1 = *reinterpret_cast<__half2*>(&hi);
    float2 f0 = __half22float2(h0), f1 = __half22float2(h1);
    return make_float4(f0.x, f0.y, f1.x, f1.y);
}

__device__ __forceinline__ void gemv32(const float4* __restrict__ sW,
                                       const float4* xr, ulonglong2* acc) {
#pragma unroll
    for (int k = 0; k < 32; k++) {
        float f = COMP(xr[k >> 2], k & 3);
        unsigned long long f2;
        asm("mov.b64 %0, {%1, %1};" : "=l"(f2) : "f"(f));
        const ulonglong2* w = (const ulonglong2*)(sW + k * 8);
#pragma unroll
        for (int i = 0; i < 8; i++) {
            ulonglong2 wv = w[i];
            asm("fma.rn.f32x2 %0, %1, %2, %0;" : "+l"(acc[i].x) : "l"(f2), "l"(wv.x));
            asm("fma.rn.f32x2 %0, %1, %2, %0;" : "+l"(acc[i].y) : "l"(f2), "l"(wv.y));
        }
    }
}

// int64 edge values < 1e5 -> odd 32-bit words all zero; int32 layout -> random nonzero
__device__ __forceinline__ int detect_i64(const int* ei32) {
    int v = ei32[2 * (threadIdx.x & 31) + 1];
    unsigned m = __ballot_sync(0xffffffffu, v != 0);
    return m == 0;
}

// ---------------- decode: dst histogram + pos packing ----------------
__global__ void decode_kernel(const void* ei, const float* __restrict__ pos) {
    int i64 = detect_i64((const int*)ei);
    int e = blockIdx.x * blockDim.x + threadIdx.x;
    if (e < N_NODES)
        g_pos4[e] = make_float4(pos[e * 3 + 0], pos[e * 3 + 1], pos[e * 3 + 2], 0.f);
    if (e >= N_EDGES) return;
    int dst;
    if (i64) dst = (int)((const long long*)ei)[N_EDGES + e];
    else     dst = ((const int*)ei)[N_EDGES + e];
    atomicAdd(&g_zero[dst], 1);
}

// ---------------- scan (decoupled lookback) + precompute, one launch ----------------
__global__ void __launch_bounds__(SCAN_T) scanpre_kernel(
    const float* __restrict__ enc_w2, const float* __restrict__ enc_b2,
    const float* __restrict__ msg_w1, const float* __restrict__ msg_b1,
    const float* __restrict__ msg_w2, const float* __restrict__ msg_b2,
    const float* __restrict__ upd_w1, const float* __restrict__ upd_b1,
    const float* __restrict__ upd_w2, const float* __restrict__ upd_b2,
    const float* __restrict__ out_w, const float* __restrict__ out_b) {
    int t = threadIdx.x;
    if (blockIdx.x >= N_PARTS) {
        int b = blockIdx.x - N_PARTS;
        if (b < 13) {
            int l = (b < 12) ? (b % 3) : 2;
            int kind = (b < 12) ? (b / 3) : 4;
            const float* Wp = (l == 0) ? enc_w2 : upd_w2 + (size_t)(l - 1) * 1024;
            const float* L; const float* R; float* P;
            switch (kind) {
                case 0: L = Wp;                      R = msg_w1 + (size_t)l * 2080;        P = c_Pa[l]; break;
                case 1: L = Wp;                      R = msg_w1 + (size_t)l * 2080 + 1024; P = c_Pb[l]; break;
                case 2: L = Wp;                      R = upd_w1 + (size_t)l * 2048;        P = c_P1[l]; break;
                case 3: L = msg_w2 + (size_t)l*1024; R = upd_w1 + (size_t)l * 2048 + 1024; P = c_P2[l]; break;
                default: L = upd_w2 + 2048;          R = out_w;                            P = c_Po;    break;
            }
            for (int e = t; e < 1024; e += SCAN_T) {
                int i = e >> 5, j = e & 31;
                float s = 0.f;
                for (int k = 0; k < 32; k++) s = fmaf(L[i * 32 + k], R[k * 32 + j], s);
                P[e] = s;
            }
        } else {
            for (int e = t; e < 416; e += SCAN_T) {
                int vid = e >> 5, j = e & 31;
                int l = vid % 3;
                const float* cp = (l == 0) ? enc_b2 : upd_b2 + (size_t)(l - 1) * 32;
                float s = 0.f;
                if (vid < 3) {
                    const float* R = msg_w1 + (size_t)l * 2080;
                    for (int k = 0; k < 32; k++) s = fmaf(cp[k], R[k * 32 + j], s);
                    c_qa[l][j] = s;
                } else if (vid < 6) {
                    const float* R = msg_w1 + (size_t)l * 2080 + 1024;
                    for (int k = 0; k < 32; k++) s = fmaf(cp[k], R[k * 32 + j], s);
                    c_qb[l][j] = s;
                } else if (vid < 9) {
                    const float* R = upd_w1 + (size_t)l * 2048;
                    for (int k = 0; k < 32; k++) s = fmaf(cp[k], R[k * 32 + j], s);
                    c_q1[l][j] = s + upd_b1[l * 32 + j];
                } else if (vid < 12) {
                    const float* R = upd_w1 + (size_t)l * 2048 + 1024;
                    const float* mb = msg_b2 + (size_t)l * 32;
                    for (int k = 0; k < 32; k++) s = fmaf(mb[k], R[k * 32 + j], s);
                    c_v[l][j] = s;
                } else {
                    const float* ub = upd_b2 + 2 * 32;
                    for (int k = 0; k < 32; k++) s = fmaf(ub[k], out_w[k * 32 + j], s);
                    c_qo[j] = s + out_b[j];
                }
            }
        }
        return;
    }

    // ---- scan part ----
    __shared__ int s[SCAN_T];
    __shared__ int s_prefix;
    unsigned long long* state = (unsigned long long*)&g_zero[N_NODES];
    int part = blockIdx.x;
    int base = part * SCAN_PART + t * SCAN_ITEMS;
    int v[SCAN_ITEMS];
    int tsum = 0;
#pragma unroll
    for (int j = 0; j < SCAN_ITEMS; j++) {
        int idx = base + j;
        v[j] = (idx < N_NODES) ? g_zero[idx] : 0;
        tsum += v[j];
    }
    s[t] = tsum;
    __syncthreads();
#pragma unroll
    for (int off = 1; off < SCAN_T; off <<= 1) {
        int tt = (t >= off) ? s[t - off] : 0;
        __syncthreads();
        s[t] += tt;
        __syncthreads();
    }
    int texcl = s[t] - tsum;
    int btotal = s[SCAN_T - 1];

    if (t == 0) {
        if (part == 0) {
            s_prefix = 0;
            atomicExch(&state[0], (2ULL << 32) | (unsigned)btotal);
        } else {
            atomicExch(&state[part], (1ULL << 32) | (unsigned)btotal);
            int pref = 0;
            int p = part - 1;
            while (true) {
                unsigned long long st;
                do { st = atomicAdd(&state[p], 0ULL); } while ((st >> 32) == 0);
                pref += (int)(unsigned)st;
                if ((st >> 32) == 2) break;
                p--;
            }
            s_prefix = pref;
            atomicExch(&state[part], (2ULL << 32) | (unsigned)(pref + btotal));
        }
    }
    __syncthreads();
    int excl = s_prefix + texcl;
#pragma unroll
    for (int j = 0; j < SCAN_ITEMS; j++) {
        int idx = base + j;
        if (idx < N_NODES) { g_off[idx] = excl; g_cur[idx] = excl; }
        excl += v[j];
    }
}

// ---------------- scatter edges into CSR order (by dst) ----------------
__global__ void scatter_kernel(const void* ei) {
    int i64 = detect_i64((const int*)ei);
    int e = blockIdx.x * blockDim.x + threadIdx.x;
    if (e >= N_EDGES) return;
    int src, dst;
    if (i64) {
        const long long* p = (const long long*)ei;
        src = (int)p[e]; dst = (int)p[N_EDGES + e];
    } else {
        const int* p = (const int*)ei;
        src = p[e]; dst = p[N_EDGES + e];
    }
    float4 pd = __ldg(&g_pos4[dst]);
    float4 ps = __ldg(&g_pos4[src]);
    float dx = pd.x - ps.x, dy = pd.y - ps.y, dz = pd.z - ps.z;
    float dist = sqrtf(dx * dx + dy * dy + dz * dz);
    int p = atomicAdd(&g_cur[dst], 1);
    g_epack[p] = make_int2(src, __float_as_int(dist));
}

// ---------------- encoder: h = relu(feat@w1+b1); A=h@Pa0+qa0; B=h@Pb0+qb0 ----------------
__global__ void __launch_bounds__(128) encoder_kernel(
    const float* __restrict__ feat,
    const float* __restrict__ w1, const float* __restrict__ b1) {
    __shared__ float  s_feat[128 * 33];
    __shared__ float4 s_w1[64 * 8];
    __shared__ float4 s_pa[256], s_pb[256];
    __shared__ float4 s_b1[8], s_qa[8], s_qb[8];
    for (int i = threadIdx.x; i < 512; i += 128) s_w1[i] = ((const float4*)w1)[i];
    for (int i = threadIdx.x; i < 256; i += 128) {
        s_pa[i] = ((const float4*)c_Pa[0])[i];
        s_pb[i] = ((const float4*)c_Pb[0])[i];
    }
    if (threadIdx.x < 8) {
        s_b1[threadIdx.x] = ((const float4*)b1)[threadIdx.x];
        s_qa[threadIdx.x] = ((const float4*)c_qa[0])[threadIdx.x];
        s_qb[threadIdx.x] = ((const float4*)c_qb[0])[threadIdx.x];
    }
    __syncthreads();
    int base = blockIdx.x * 128;
    int n = base + threadIdx.x;
    bool act = (n < N_NODES);

    ulonglong2 hacc[8];
#pragma unroll
    for (int i = 0; i < 8; i++) hacc[i] = pack4(s_b1[i]);

#pragma unroll
    for (int half = 0; half < 2; half++) {
        for (int j = threadIdx.x; j < 128 * 32; j += 128) {
            int r = j >> 5, col = j & 31;
            int nn = base + r;
            s_feat[r * 33 + col] =
                (nn < N_NODES) ? feat[(size_t)nn * 64 + half * 32 + col] : 0.f;
        }
        __syncthreads();
        const float* frow = &s_feat[threadIdx.x * 33];
#pragma unroll 8
        for (int k = 0; k < 32; k++) {
            float f = frow[k];
            unsigned long long f2;
            asm("mov.b64 %0, {%1, %1};" : "=l"(f2) : "f"(f));
            const ulonglong2* w = (const ulonglong2*)(s_w1 + (half * 32 + k) * 8);
#pragma unroll
            for (int i = 0; i < 8; i++) {
                ulonglong2 wv = w[i];
                asm("fma.rn.f32x2 %0, %1, %2, %0;" : "+l"(hacc[i].x) : "l"(f2), "l"(wv.x));
                asm("fma.rn.f32x2 %0, %1, %2, %0;" : "+l"(hacc[i].y) : "l"(f2), "l"(wv.y));
            }
        }
        __syncthreads();
    }
    float4 h[8];
#pragma unroll
    for (int i = 0; i < 8; i++) h[i] = relu4(unpack4(hacc[i]));

    ulonglong2 a[8], b[8];
#pragma unroll
    for (int i = 0; i < 8; i++) { a[i] = pack4(s_qa[i]); b[i] = pack4(s_qb[i]); }
    gemv32(s_pa, h, a);
    gemv32(s_pb, h, b);

    if (act) {
        ulonglong2* ph = (ulonglong2*)&g_h[(size_t)n * 8];
        ulonglong2* pa = (ulonglong2*)&g_A[(size_t)n * 8];
#pragma unroll
        for (int i = 0; i < 8; i++) {
            ph[i] = pack4(h[i]);
            pa[i] = a[i];
            g_Bh[(size_t)n * 8 + i] = f4_to_h4(unpack4(b[i]));
        }
    }
}

// ---------------- per layer: agg[n] = sum_e relu(A[n] + B[src_e] + d_e*c + b1) ----------------
__global__ void __launch_bounds__(256) agg_kernel(
    const float* __restrict__ w1c, const float* __restrict__ b1) {
    int n = (blockIdx.x * 256 + threadIdx.x) >> 5;
    if (n >= N_NODES) return;
    int lane = threadIdx.x & 31;
    int c = lane & 7;
    int slot = lane >> 3;

    float4 cv = __ldg(((const float4*)w1c) + c);
    float4 bb = __ldg(((const float4*)b1) + c);

    int start = __ldg(&g_off[n]);
    int end = start + __ldg(&g_zero[n]);   // g_zero = hist

    float4 ab = add4(g_A[(size_t)n * 8 + c], bb);
    float4 acc0 = make_float4(0.f, 0.f, 0.f, 0.f);
    float4 acc1 = make_float4(0.f, 0.f, 0.f, 0.f);

    int i = start + slot;
    for (; i + 4 < end; i += 8) {
        int2 sd0 = __ldg(&g_epack[i]);
        int2 sd1 = __ldg(&g_epack[i + 4]);
        float4 b0 = h4_to_f4(__ldg(&g_Bh[(size_t)sd0.x * 8 + c]));
        float4 b1v = h4_to_f4(__ldg(&g_Bh[(size_t)sd1.x * 8 + c]));
        acc0 = add4(acc0, relu4(fma4(__int_as_float(sd0.y), cv, add4(ab, b0))));
        acc1 = add4(acc1, relu4(fma4(__int_as_float(sd1.y), cv, add4(ab, b1v))));
    }
    if (i < end) {
        int2 sd = __ldg(&g_epack[i]);
        float4 b = h4_to_f4(__ldg(&g_Bh[(size_t)sd.x * 8 + c]));
        acc0 = add4(acc0, relu4(fma4(__int_as_float(sd.y), cv, add4(ab, b))));
    }
    float4 acc = add4(acc0, acc1);
#pragma unroll
    for (int m = 8; m <= 16; m <<= 1) {
        acc.x += __shfl_xor_sync(0xffffffffu, acc.x, m);
        acc.y += __shfl_xor_sync(0xffffffffu, acc.y, m);
        acc.z += __shfl_xor_sync(0xffffffffu, acc.z, m);
        acc.w += __shfl_xor_sync(0xffffffffu, acc.w, m);
    }
    if (lane < 8) g_agg[(size_t)n * 8 + lane] = acc;
}

// ---------------- per layer update (folded) ----------------
__global__ void __launch_bounds__(128) update_kernel(int l, int last, float* __restrict__ outp) {
    __shared__ float4 s_p1[256], s_p2[256], s_pc[256], s_pd[256];
    __shared__ float4 s_q1[8], s_v[8], s_qc[8], s_qd[8];
    {
        const float* P1 = c_P1[l];
        const float* P2 = c_P2[l];
        const float* Pc = last ? c_Po : c_Pa[l + 1 < 3 ? l + 1 : 0];
        const float* Pd = last ? c_Po : c_Pb[l + 1 < 3 ? l + 1 : 0];
        for (int i = threadIdx.x; i < 256; i += 128) {
            s_p1[i] = ((const float4*)P1)[i];
            s_p2[i] = ((const float4*)P2)[i];
            s_pc[i] = ((const float4*)Pc)[i];
            s_pd[i] = ((const float4*)Pd)[i];
        }
        if (threadIdx.x < 8) {
            s_q1[threadIdx.x] = ((const float4*)c_q1[l])[threadIdx.x];
            s_v[threadIdx.x]  = ((const float4*)c_v[l])[threadIdx.x];
            const float* qc = last ? c_qo : c_qa[l + 1 < 3 ? l + 1 : 0];
            const float* qd = last ? c_qo : c_qb[l + 1 < 3 ? l + 1 : 0];
            s_qc[threadIdx.x] = ((const float4*)qc)[threadIdx.x];
            s_qd[threadIdx.x] = ((const float4*)qd)[threadIdx.x];
        }
    }
    __syncthreads();
    int n = blockIdx.x * blockDim.x + threadIdx.x;
    if (n >= N_NODES) return;

    float deg = (float)g_zero[n];
    ulonglong2 uacc[8];
#pragma unroll
    for (int i = 0; i < 8; i++) {
        float4 q = s_q1[i], vv = s_v[i];
        uacc[i] = pack4(make_float4(fmaf(deg, vv.x, q.x), fmaf(deg, vv.y, q.y),
                                    fmaf(deg, vv.z, q.z), fmaf(deg, vv.w, q.w)));
    }
    float4 hr[8];
#pragma unroll
    for (int i = 0; i < 8; i++) hr[i] = g_h[(size_t)n * 8 + i];
    gemv32(s_p1, hr, uacc);
    float4 ar[8];
#pragma unroll
    for (int i = 0; i < 8; i++) ar[i] = g_agg[(size_t)n * 8 + i];
    gemv32(s_p2, ar, uacc);

    float4 u[8];
#pragma unroll
    for (int i = 0; i < 8; i++) u[i] = relu4(unpack4(uacc[i]));

    ulonglong2 cacc[8];
#pragma unroll
    for (int i = 0; i < 8; i++) cacc[i] = pack4(s_qc[i]);
    gemv32(s_pc, u, cacc);

    if (!last) {
        ulonglong2 dacc[8];
#pragma unroll
        for (int i = 0; i < 8; i++) dacc[i] = pack4(s_qd[i]);
        gemv32(s_pd, u, dacc);
        ulonglong2* ph = (ulonglong2*)&g_h[(size_t)n * 8];
        ulonglong2* pa = (ulonglong2*)&g_A[(size_t)n * 8];
#pragma unroll
        for (int i = 0; i < 8; i++) {
            ph[i] = pack4(u[i]);
            pa[i] = cacc[i];
            g_Bh[(size_t)n * 8 + i] = f4_to_h4(unpack4(dacc[i]));
        }
    } else {
        ulonglong2* orow = (ulonglong2*)(outp + (size_t)n * 32);
#pragma unroll
        for (int i = 0; i < 8; i++) orow[i] = cacc[i];
    }
}

// ---------------- launch ----------------
extern "C" void kernel_launch(void* const* d_in, const int* in_sizes, int n_in,
                              void* d_out, int out_size) {
    const float* node_feat = (const float*)d_in[0];
    const float* pos       = (const float*)d_in[1];
    const void*  ei        = d_in[2];
    const float* enc_w1    = (const float*)d_in[3];
    const float* enc_b1    = (const float*)d_in[4];
    const float* enc_w2    = (const float*)d_in[5];
    const float* enc_b2    = (const float*)d_in[6];
    const float* msg_w1    = (const float*)d_in[7];
    const float* msg_b1    = (const float*)d_in[8];
    const float* msg_w2    = (const float*)d_in[9];
    const float* msg_b2    = (const float*)d_in[10];
    const float* upd_w1    = (const float*)d_in[11];
    const float* upd_b1    = (const float*)d_in[12];
    const float* upd_w2    = (const float*)d_in[13];
    const float* upd_b2    = (const float*)d_in[14];
    const float* out_w     = (const float*)d_in[15];
    const float* out_b     = (const float*)d_in[16];
    float* out = (float*)d_out;

    const int NODE_BLOCKS = (N_NODES + 127) / 128;
    const int EDGE_BLOCKS = (N_EDGES + 255) / 256;
    const int AGG_BLOCKS  = (N_NODES * 32 + 255) / 256;

    // single memset node: hist + scan state
    void* p_zero = nullptr;
    cudaGetSymbolAddress(&p_zero, g_zero);
    cudaMemsetAsync(p_zero, 0, (N_NODES + 2 * N_PARTS) * sizeof(int), 0);

    decode_kernel<<<EDGE_BLOCKS, 256>>>(ei, pos);                       // idx 1
    scanpre_kernel<<<N_PARTS + 14, SCAN_T>>>(enc_w2, enc_b2,            // idx 2
        msg_w1, msg_b1, msg_w2, msg_b2, upd_w1, upd_b1, upd_w2, upd_b2, out_w, out_b);
    scatter_kernel<<<EDGE_BLOCKS, 256>>>(ei);                           // idx 3
    encoder_kernel<<<NODE_BLOCKS, 128>>>(node_feat, enc_w1, enc_b1);    // idx 4

    for (int l = 0; l < 3; l++) {
        const float* w1 = msg_w1 + (size_t)l * 65 * 32;
        agg_kernel<<<AGG_BLOCKS, 256>>>(w1 + 64 * 32, msg_b1 + (size_t)l * 32);  // l=0 -> idx 5 (profiled)
        update_kernel<<<NODE_BLOCKS, 128>>>(l, l == 2, out);
    }
}